// round 8
// baseline (speedup 1.0000x reference)
#include <cuda_runtime.h>
#include <cstdint>

// Problem constants
#define Bz   8192
#define Tz   512
#define Dz   8
#define Hz   64
#define Gz   256      // 4*H
#define BT   64       // batch tile per CTA
#define NCTA 128      // Bz / BT
#define NTHR 256

// SMEM layout (floats)
#define XROWS   72            // dec layer0 input = cat(x[8], y_prev[64])
#define RS      68            // row stride for xs/hs (16B aligned rows)
#define GSTR    66            // gs row stride (8B aligned, 2-way conflicts only)
#define XS_F    (XROWS*RS)            // 4896
#define HS_F    (3*Hz*RS)             // 13056
#define CS_F    (3*Hz*BT)             // 12288
#define GS_F    (Gz*GSTR)             // 16896
#define FW_F    (Dz*Hz)               // 512
#define SMEM_FLOATS (XS_F + HS_F + CS_F + GS_F + FW_F + 16)
#define SMEM_BYTES  (SMEM_FLOATS * 4)

typedef unsigned long long u64;

// Pre-transposed, pre-duplicated weights: element (k2*256 + j) holds
// { {w[j][2k2], w[j][2k2]}, {w[j][2k2+1], w[j][2k2+1]} }
__device__ ulonglong2 g_wt[92160];   // 1.44 MB

// offsets (ulonglong2 units) per matrix, fan2*256 each
#define O_EI0 0        // fan2=4
#define O_EH0 1024     // 32
#define O_EI1 9216     // 32
#define O_EH1 17408    // 32
#define O_EI2 25600    // 32
#define O_EH2 33792    // 32
#define O_DI0 41984    // 36
#define O_DH0 51200    // 32
#define O_DI1 59392    // 32
#define O_DH1 67584    // 32
#define O_DI2 75776    // 32
#define O_DH2 83968    // 32

// ---------------- helpers ----------------
__device__ __forceinline__ u64 pack2(float x, float y) {
    u64 r;
    asm("mov.b64 %0, {%1, %2};" : "=l"(r) : "r"(__float_as_uint(x)), "r"(__float_as_uint(y)));
    return r;
}
__device__ __forceinline__ void ffma2(u64& a, u64 w, u64 v) {
    asm("fma.rn.f32x2 %0, %1, %2, %0;" : "+l"(a) : "l"(w), "l"(v));
}
__device__ __forceinline__ float tanhx(float x) {
    float r;
    asm("tanh.approx.f32 %0, %1;" : "=f"(r) : "f"(x));
    return r;
}
__device__ __forceinline__ float sigx(float x) {
    return fmaf(tanhx(0.5f * x), 0.5f, 0.5f);
}

// ---------------- weight prep ----------------
__global__ void prep_kernel(const float* __restrict__ W, int fan, int off) {
    int id = blockIdx.x * 256 + threadIdx.x;   // id = k2*256 + j ; grid.x == fan/2
    int k2 = id >> 8, j = id & 255;
    float w0 = W[j * fan + 2 * k2];
    float w1 = W[j * fan + 2 * k2 + 1];
    ulonglong2 o;
    o.x = pack2(w0, w0);
    o.y = pack2(w1, w1);
    g_wt[off + id] = o;
}

// ---------------- gate accumulation ----------------
// acc[b] += W[row][k] * s[k][b]; thread handles rows jj and jj+128, batches [ho, ho+32)
template<int FAN2>
__device__ __forceinline__ void accum_mat(const ulonglong2* __restrict__ Wt, int jj,
                                          const float* __restrict__ s, int ho,
                                          u64* __restrict__ accA, u64* __restrict__ accB) {
    const ulonglong2* pA = Wt + jj;
    const ulonglong2* pB = Wt + jj + 128;
    ulonglong2 bufA[2], bufB[2];
    bufA[0] = pA[0]; bufB[0] = pB[0];
    if (FAN2 > 1) { bufA[1] = pA[256]; bufB[1] = pB[256]; }
    #pragma unroll 2
    for (int k2 = 0; k2 < FAN2; ++k2) {
        ulonglong2 wA = bufA[k2 & 1], wB = bufB[k2 & 1];
        if (k2 + 2 < FAN2) {
            bufA[k2 & 1] = pA[(k2 + 2) * 256];
            bufB[k2 & 1] = pB[(k2 + 2) * 256];
        }
        const ulonglong2* s0 = (const ulonglong2*)(s + (2 * k2) * RS + ho);
        const ulonglong2* s1 = (const ulonglong2*)(s + (2 * k2 + 1) * RS + ho);
        #pragma unroll
        for (int q = 0; q < 8; ++q) {
            ulonglong2 v0 = s0[q];
            ffma2(accA[2 * q],     wA.x, v0.x);
            ffma2(accA[2 * q + 1], wA.x, v0.y);
            ffma2(accB[2 * q],     wB.x, v0.x);
            ffma2(accB[2 * q + 1], wB.x, v0.y);
            ulonglong2 v1 = s1[q];
            ffma2(accA[2 * q],     wA.y, v1.x);
            ffma2(accA[2 * q + 1], wA.y, v1.y);
            ffma2(accB[2 * q],     wB.y, v1.x);
            ffma2(accB[2 * q + 1], wB.y, v1.y);
        }
    }
}

template<int FANIH2>
__device__ __forceinline__ void layer_gates(int tid,
                                            const ulonglong2* __restrict__ WtIh,
                                            const ulonglong2* __restrict__ WtHh,
                                            const float* __restrict__ bias,
                                            const float* __restrict__ in_s,
                                            const float* __restrict__ h_s,
                                            float* __restrict__ gs) {
    int jj = tid & 127, half = tid >> 7, ho = half * 32;
    u64 accA[16], accB[16];
    float bA = bias[jj], bB = bias[jj + 128];
    u64 bpA = pack2(bA, bA), bpB = pack2(bB, bB);
    #pragma unroll
    for (int i = 0; i < 16; ++i) { accA[i] = bpA; accB[i] = bpB; }
    accum_mat<FANIH2>(WtIh, jj, in_s, ho, accA, accB);
    accum_mat<32>(WtHh, jj, h_s, ho, accA, accB);
    float* gA = gs + jj * GSTR + ho;
    float* gB = gs + (jj + 128) * GSTR + ho;
    #pragma unroll
    for (int q = 0; q < 16; ++q) {
        *(u64*)(gA + 2 * q) = accA[q];   // {b_even, b_odd} little-endian == gs[b], gs[b+1]
        *(u64*)(gB + 2 * q) = accB[q];
    }
}

// LSTM pointwise epilogue: thread handles unit u = tid&63, batch group tid>>6 (16 b each)
__device__ __forceinline__ void layer_epilogue(int tid,
                                               const float* __restrict__ gs,
                                               float* __restrict__ c_s,   // [b*64+u]
                                               float* __restrict__ h_s,   // [u*RS+b]
                                               float* __restrict__ y_s) { // optional copy
    int u = tid & 63, grp = tid >> 6;
    #pragma unroll 4
    for (int bi = 0; bi < 16; ++bi) {
        int b = grp * 16 + bi;
        float gi = gs[u * GSTR + b];
        float gf = gs[(u + 64) * GSTR + b];
        float gg = gs[(u + 128) * GSTR + b];
        float go = gs[(u + 192) * GSTR + b];
        float c  = c_s[b * Hz + u];
        float cn = sigx(gf) * c + sigx(gi) * tanhx(gg);
        float hn = sigx(go) * tanhx(cn);
        c_s[b * Hz + u] = cn;
        h_s[u * RS + b] = hn;
        if (y_s) y_s[u * RS + b] = hn;
    }
}

// Final FC: pred[b][d] = h[b] . fc_W[d] + fc_b[d]
__device__ __forceinline__ void fc_store(int tid,
                                         const float* __restrict__ h_s,
                                         const float* __restrict__ fw,
                                         const float* __restrict__ fb,
                                         float* __restrict__ out,
                                         int b0, int t) {
    int b = tid & 63, dd = tid >> 6;  // dd in 0..3, handles d=dd and d=dd+4
    float a0 = fb[dd], a1 = fb[dd + 4];
    #pragma unroll
    for (int u = 0; u < Hz; ++u) {
        float h = h_s[u * RS + b];
        a0 = fmaf(fw[dd * Hz + u], h, a0);
        a1 = fmaf(fw[(dd + 4) * Hz + u], h, a1);
    }
    float* o = out + ((size_t)(b0 + b) * Tz + t) * Dz;
    o[dd]     = a0;
    o[dd + 4] = a1;
}

__global__ void __launch_bounds__(NTHR, 1)
seq2seq_kernel(const float* __restrict__ enc_x, const float* __restrict__ dec_x,
               const float* __restrict__ eb0, const float* __restrict__ eb1, const float* __restrict__ eb2,
               const float* __restrict__ db0, const float* __restrict__ db1, const float* __restrict__ db2,
               const float* __restrict__ fcW, const float* __restrict__ fcb,
               float* __restrict__ out) {
    extern __shared__ float sm[];
    float* xs = sm;                 // [XROWS][RS] layer-0 input, transposed
    float* hs = xs + XS_F;          // 3 x [64][RS] h state, transposed
    float* cs = hs + HS_F;          // 3 x [b*64+u]
    float* gs = cs + CS_F;          // [256][GSTR]
    float* fw = gs + GS_F;
    float* fb = fw + FW_F;

    const int tid = threadIdx.x;
    const int b0  = blockIdx.x * BT;

    for (int i = tid; i < HS_F; i += NTHR) hs[i] = 0.f;
    for (int i = tid; i < CS_F; i += NTHR) cs[i] = 0.f;
    for (int i = tid; i < FW_F; i += NTHR) fw[i] = fcW[i];
    if (tid < Dz) fb[tid] = fcb[tid];
    __syncthreads();

    float* hs0 = hs;          float* hs1 = hs + Hz * RS;  float* hs2 = hs + 2 * Hz * RS;
    float* cs0 = cs;          float* cs1 = cs + Hz * BT;  float* cs2 = cs + 2 * Hz * BT;

    // ---------------- encoder ----------------
    {
        const ulonglong2* WI0 = g_wt + O_EI0; const ulonglong2* WH0 = g_wt + O_EH0;
        const ulonglong2* WI1 = g_wt + O_EI1; const ulonglong2* WH1 = g_wt + O_EH1;
        const ulonglong2* WI2 = g_wt + O_EI2; const ulonglong2* WH2 = g_wt + O_EH2;

        #pragma unroll 1
        for (int t = 0; t < Tz; ++t) {
            {
                int b = tid & 63, k = tid >> 6;
                const float* src = enc_x + ((size_t)(b0 + b) * Tz + t) * Dz;
                xs[k * RS + b]       = src[k];
                xs[(k + 4) * RS + b] = src[k + 4];
            }
            __syncthreads();
            layer_gates<4>(tid, WI0, WH0, eb0, xs, hs0, gs);
            __syncthreads();
            layer_epilogue(tid, gs, cs0, hs0, (float*)0);
            __syncthreads();
            layer_gates<32>(tid, WI1, WH1, eb1, hs0, hs1, gs);
            __syncthreads();
            layer_epilogue(tid, gs, cs1, hs1, (float*)0);
            __syncthreads();
            layer_gates<32>(tid, WI2, WH2, eb2, hs1, hs2, gs);
            __syncthreads();
            layer_epilogue(tid, gs, cs2, hs2, (float*)0);
            __syncthreads();
        }
    }

    // ---------------- decoder ----------------
    {
        const ulonglong2* WI0 = g_wt + O_DI0; const ulonglong2* WH0 = g_wt + O_DH0;
        const ulonglong2* WI1 = g_wt + O_DI1; const ulonglong2* WH1 = g_wt + O_DH1;
        const ulonglong2* WI2 = g_wt + O_DI2; const ulonglong2* WH2 = g_wt + O_DH2;
        float* ybuf = xs + Dz * RS;

        for (int i = tid; i < Hz * RS; i += NTHR) ybuf[i] = 0.f;  // y_prev = 0
        __syncthreads();

        #pragma unroll 1
        for (int t = 0; t < Tz; ++t) {
            {
                int b = tid & 63, k = tid >> 6;
                const float* src = dec_x + ((size_t)(b0 + b) * Tz + t) * Dz;
                xs[k * RS + b]       = src[k];
                xs[(k + 4) * RS + b] = src[k + 4];
            }
            __syncthreads();
            layer_gates<36>(tid, WI0, WH0, db0, xs, hs0, gs);
            __syncthreads();
            layer_epilogue(tid, gs, cs0, hs0, (float*)0);
            __syncthreads();
            layer_gates<32>(tid, WI1, WH1, db1, hs0, hs1, gs);
            __syncthreads();
            layer_epilogue(tid, gs, cs1, hs1, (float*)0);
            __syncthreads();
            layer_gates<32>(tid, WI2, WH2, db2, hs1, hs2, gs);
            __syncthreads();
            layer_epilogue(tid, gs, cs2, hs2, ybuf);
            __syncthreads();

            fc_store(tid, hs2, fw, fb, out, b0, t);
        }
    }
}

extern "C" void kernel_launch(void* const* d_in, const int* in_sizes, int n_in,
                              void* d_out, int out_size) {
    (void)in_sizes; (void)n_in; (void)out_size;
    const float* enc_x = (const float*)d_in[0];
    const float* dec_x = (const float*)d_in[1];
    const float* eWih0 = (const float*)d_in[2];
    const float* eWhh0 = (const float*)d_in[3];
    const float* eb0   = (const float*)d_in[4];
    const float* eWih1 = (const float*)d_in[5];
    const float* eWhh1 = (const float*)d_in[6];
    const float* eb1   = (const float*)d_in[7];
    const float* eWih2 = (const float*)d_in[8];
    const float* eWhh2 = (const float*)d_in[9];
    const float* eb2   = (const float*)d_in[10];
    const float* dWih0 = (const float*)d_in[11];
    const float* dWhh0 = (const float*)d_in[12];
    const float* db0   = (const float*)d_in[13];
    const float* dWih1 = (const float*)d_in[14];
    const float* dWhh1 = (const float*)d_in[15];
    const float* db1   = (const float*)d_in[16];
    const float* dWih2 = (const float*)d_in[17];
    const float* dWhh2 = (const float*)d_in[18];
    const float* db2   = (const float*)d_in[19];
    const float* fcW   = (const float*)d_in[20];
    const float* fcb   = (const float*)d_in[21];
    float* out = (float*)d_out;

    // weight transpose+duplicate prep (12 tiny launches, graph-capturable)
    prep_kernel<<< 4, 256>>>(eWih0,  8, O_EI0);
    prep_kernel<<<32, 256>>>(eWhh0, 64, O_EH0);
    prep_kernel<<<32, 256>>>(eWih1, 64, O_EI1);
    prep_kernel<<<32, 256>>>(eWhh1, 64, O_EH1);
    prep_kernel<<<32, 256>>>(eWih2, 64, O_EI2);
    prep_kernel<<<32, 256>>>(eWhh2, 64, O_EH2);
    prep_kernel<<<36, 256>>>(dWih0, 72, O_DI0);
    prep_kernel<<<32, 256>>>(dWhh0, 64, O_DH0);
    prep_kernel<<<32, 256>>>(dWih1, 64, O_DI1);
    prep_kernel<<<32, 256>>>(dWhh1, 64, O_DH1);
    prep_kernel<<<32, 256>>>(dWih2, 64, O_DI2);
    prep_kernel<<<32, 256>>>(dWhh2, 64, O_DH2);

    cudaFuncSetAttribute(seq2seq_kernel,
                         cudaFuncAttributeMaxDynamicSharedMemorySize, SMEM_BYTES);
    seq2seq_kernel<<<NCTA, NTHR, SMEM_BYTES>>>(
        enc_x, dec_x, eb0, eb1, eb2, db0, db1, db2, fcW, fcb, out);
}

// round 9
// speedup vs baseline: 1.0010x; 1.0010x over previous
#include <cuda_runtime.h>
#include <cstdint>

// Problem constants
#define Bz   8192
#define Tz   512
#define Dz   8
#define Hz   64
#define Gz   256      // 4*H
#define BT   64       // batch tile per CTA
#define NCTA 128      // Bz / BT
#define NTHR 256

// SMEM layout (floats)
#define XROWS   72            // dec layer0 input = cat(x[8], y_prev[64])
#define RS      68            // row stride for xs/hs (16B aligned rows)
#define GSTR    66            // gs row stride (8B aligned, 2-way conflicts only)
#define XS_F    (XROWS*RS)            // 4896
#define HS_F    (3*Hz*RS)             // 13056
#define CS_F    (3*Hz*BT)             // 12288
#define GS_F    (Gz*GSTR)             // 16896
#define FW_F    (Dz*Hz)               // 512
#define SMEM_FLOATS (XS_F + HS_F + CS_F + GS_F + FW_F + 16)
#define SMEM_BYTES  (SMEM_FLOATS * 4)

typedef unsigned long long u64;

// Pre-transposed, pre-duplicated weights: element (k2*256 + j) holds
// { {w[j][2k2], w[j][2k2]}, {w[j][2k2+1], w[j][2k2+1]} }
__device__ ulonglong2 g_wt[92160];   // 1.44 MB

// offsets (ulonglong2 units) per matrix, fan2*256 each
#define O_EI0 0        // fan2=4
#define O_EH0 1024     // 32
#define O_EI1 9216     // 32
#define O_EH1 17408    // 32
#define O_EI2 25600    // 32
#define O_EH2 33792    // 32
#define O_DI0 41984    // 36
#define O_DH0 51200    // 32
#define O_DI1 59392    // 32
#define O_DH1 67584    // 32
#define O_DI2 75776    // 32
#define O_DH2 83968    // 32

// ---------------- helpers ----------------
__device__ __forceinline__ u64 pack2(float x, float y) {
    u64 r;
    asm("mov.b64 %0, {%1, %2};" : "=l"(r) : "r"(__float_as_uint(x)), "r"(__float_as_uint(y)));
    return r;
}
__device__ __forceinline__ void ffma2(u64& a, u64 w, u64 v) {
    asm("fma.rn.f32x2 %0, %1, %2, %0;" : "+l"(a) : "l"(w), "l"(v));
}
__device__ __forceinline__ float tanhx(float x) {
    float r;
    asm("tanh.approx.f32 %0, %1;" : "=f"(r) : "f"(x));
    return r;
}
__device__ __forceinline__ float sigx(float x) {
    return fmaf(tanhx(0.5f * x), 0.5f, 0.5f);
}

// ---------------- weight prep ----------------
__global__ void prep_kernel(const float* __restrict__ W, int fan, int off) {
    int id = blockIdx.x * 256 + threadIdx.x;   // id = k2*256 + j ; grid.x == fan/2
    int k2 = id >> 8, j = id & 255;
    float w0 = W[j * fan + 2 * k2];
    float w1 = W[j * fan + 2 * k2 + 1];
    ulonglong2 o;
    o.x = pack2(w0, w0);
    o.y = pack2(w1, w1);
    g_wt[off + id] = o;
}

// ---------------- gate accumulation ----------------
// acc[b] += W[row][k] * s[k][b]; thread handles rows jj and jj+128, batches [ho, ho+32)
template<int FAN2>
__device__ __forceinline__ void accum_mat(const ulonglong2* __restrict__ Wt, int jj,
                                          const float* __restrict__ s, int ho,
                                          u64* __restrict__ accA, u64* __restrict__ accB) {
    const ulonglong2* pA = Wt + jj;
    const ulonglong2* pB = Wt + jj + 128;
    ulonglong2 bufA[2], bufB[2];
    bufA[0] = pA[0]; bufB[0] = pB[0];
    if (FAN2 > 1) { bufA[1] = pA[256]; bufB[1] = pB[256]; }
    #pragma unroll 2
    for (int k2 = 0; k2 < FAN2; ++k2) {
        ulonglong2 wA = bufA[k2 & 1], wB = bufB[k2 & 1];
        if (k2 + 2 < FAN2) {
            bufA[k2 & 1] = pA[(k2 + 2) * 256];
            bufB[k2 & 1] = pB[(k2 + 2) * 256];
        }
        const ulonglong2* s0 = (const ulonglong2*)(s + (2 * k2) * RS + ho);
        const ulonglong2* s1 = (const ulonglong2*)(s + (2 * k2 + 1) * RS + ho);
        #pragma unroll
        for (int q = 0; q < 8; ++q) {
            ulonglong2 v0 = s0[q];
            ffma2(accA[2 * q],     wA.x, v0.x);
            ffma2(accA[2 * q + 1], wA.x, v0.y);
            ffma2(accB[2 * q],     wB.x, v0.x);
            ffma2(accB[2 * q + 1], wB.x, v0.y);
            ulonglong2 v1 = s1[q];
            ffma2(accA[2 * q],     wA.y, v1.x);
            ffma2(accA[2 * q + 1], wA.y, v1.y);
            ffma2(accB[2 * q],     wB.y, v1.x);
            ffma2(accB[2 * q + 1], wB.y, v1.y);
        }
    }
}

template<int FANIH2>
__device__ __forceinline__ void layer_gates(int tid,
                                            const ulonglong2* __restrict__ WtIh,
                                            const ulonglong2* __restrict__ WtHh,
                                            const float* __restrict__ bias,
                                            const float* __restrict__ in_s,
                                            const float* __restrict__ h_s,
                                            float* __restrict__ gs) {
    int jj = tid & 127, half = tid >> 7, ho = half * 32;
    u64 accA[16], accB[16];
    float bA = bias[jj], bB = bias[jj + 128];
    u64 bpA = pack2(bA, bA), bpB = pack2(bB, bB);
    #pragma unroll
    for (int i = 0; i < 16; ++i) { accA[i] = bpA; accB[i] = bpB; }
    accum_mat<FANIH2>(WtIh, jj, in_s, ho, accA, accB);
    accum_mat<32>(WtHh, jj, h_s, ho, accA, accB);
    float* gA = gs + jj * GSTR + ho;
    float* gB = gs + (jj + 128) * GSTR + ho;
    #pragma unroll
    for (int q = 0; q < 16; ++q) {
        *(u64*)(gA + 2 * q) = accA[q];   // {b_even, b_odd} little-endian == gs[b], gs[b+1]
        *(u64*)(gB + 2 * q) = accB[q];
    }
}

// LSTM pointwise epilogue: thread handles unit u = tid&63, batch group tid>>6 (16 b each)
__device__ __forceinline__ void layer_epilogue(int tid,
                                               const float* __restrict__ gs,
                                               float* __restrict__ c_s,   // [b*64+u]
                                               float* __restrict__ h_s,   // [u*RS+b]
                                               float* __restrict__ y_s) { // optional copy
    int u = tid & 63, grp = tid >> 6;
    #pragma unroll 4
    for (int bi = 0; bi < 16; ++bi) {
        int b = grp * 16 + bi;
        float gi = gs[u * GSTR + b];
        float gf = gs[(u + 64) * GSTR + b];
        float gg = gs[(u + 128) * GSTR + b];
        float go = gs[(u + 192) * GSTR + b];
        float c  = c_s[b * Hz + u];
        float cn = sigx(gf) * c + sigx(gi) * tanhx(gg);
        float hn = sigx(go) * tanhx(cn);
        c_s[b * Hz + u] = cn;
        h_s[u * RS + b] = hn;
        if (y_s) y_s[u * RS + b] = hn;
    }
}

// Final FC: pred[b][d] = h[b] . fc_W[d] + fc_b[d]
__device__ __forceinline__ void fc_store(int tid,
                                         const float* __restrict__ h_s,
                                         const float* __restrict__ fw,
                                         const float* __restrict__ fb,
                                         float* __restrict__ out,
                                         int b0, int t) {
    int b = tid & 63, dd = tid >> 6;  // dd in 0..3, handles d=dd and d=dd+4
    float a0 = fb[dd], a1 = fb[dd + 4];
    #pragma unroll
    for (int u = 0; u < Hz; ++u) {
        float h = h_s[u * RS + b];
        a0 = fmaf(fw[dd * Hz + u], h, a0);
        a1 = fmaf(fw[(dd + 4) * Hz + u], h, a1);
    }
    float* o = out + ((size_t)(b0 + b) * Tz + t) * Dz;
    o[dd]     = a0;
    o[dd + 4] = a1;
}

__global__ void __launch_bounds__(NTHR, 1)
seq2seq_kernel(const float* __restrict__ enc_x, const float* __restrict__ dec_x,
               const float* __restrict__ eb0, const float* __restrict__ eb1, const float* __restrict__ eb2,
               const float* __restrict__ db0, const float* __restrict__ db1, const float* __restrict__ db2,
               const float* __restrict__ fcW, const float* __restrict__ fcb,
               float* __restrict__ out) {
    extern __shared__ float sm[];
    float* xs = sm;                 // [XROWS][RS] layer-0 input, transposed
    float* hs = xs + XS_F;          // 3 x [64][RS] h state, transposed
    float* cs = hs + HS_F;          // 3 x [b*64+u]
    float* gs = cs + CS_F;          // [256][GSTR]
    float* fw = gs + GS_F;
    float* fb = fw + FW_F;

    const int tid = threadIdx.x;
    const int b0  = blockIdx.x * BT;

    for (int i = tid; i < HS_F; i += NTHR) hs[i] = 0.f;
    for (int i = tid; i < CS_F; i += NTHR) cs[i] = 0.f;
    for (int i = tid; i < FW_F; i += NTHR) fw[i] = fcW[i];
    if (tid < Dz) fb[tid] = fcb[tid];
    __syncthreads();

    float* hs0 = hs;          float* hs1 = hs + Hz * RS;  float* hs2 = hs + 2 * Hz * RS;
    float* cs0 = cs;          float* cs1 = cs + Hz * BT;  float* cs2 = cs + 2 * Hz * BT;

    // ---------------- encoder ----------------
    {
        const ulonglong2* WI0 = g_wt + O_EI0; const ulonglong2* WH0 = g_wt + O_EH0;
        const ulonglong2* WI1 = g_wt + O_EI1; const ulonglong2* WH1 = g_wt + O_EH1;
        const ulonglong2* WI2 = g_wt + O_EI2; const ulonglong2* WH2 = g_wt + O_EH2;

        #pragma unroll 1
        for (int t = 0; t < Tz; ++t) {
            {
                int b = tid & 63, k = tid >> 6;
                const float* src = enc_x + ((size_t)(b0 + b) * Tz + t) * Dz;
                xs[k * RS + b]       = src[k];
                xs[(k + 4) * RS + b] = src[k + 4];
            }
            __syncthreads();
            layer_gates<4>(tid, WI0, WH0, eb0, xs, hs0, gs);
            __syncthreads();
            layer_epilogue(tid, gs, cs0, hs0, (float*)0);
            __syncthreads();
            layer_gates<32>(tid, WI1, WH1, eb1, hs0, hs1, gs);
            __syncthreads();
            layer_epilogue(tid, gs, cs1, hs1, (float*)0);
            __syncthreads();
            layer_gates<32>(tid, WI2, WH2, eb2, hs1, hs2, gs);
            __syncthreads();
            layer_epilogue(tid, gs, cs2, hs2, (float*)0);
            __syncthreads();
        }
    }

    // ---------------- decoder ----------------
    {
        const ulonglong2* WI0 = g_wt + O_DI0; const ulonglong2* WH0 = g_wt + O_DH0;
        const ulonglong2* WI1 = g_wt + O_DI1; const ulonglong2* WH1 = g_wt + O_DH1;
        const ulonglong2* WI2 = g_wt + O_DI2; const ulonglong2* WH2 = g_wt + O_DH2;
        float* ybuf = xs + Dz * RS;

        for (int i = tid; i < Hz * RS; i += NTHR) ybuf[i] = 0.f;  // y_prev = 0
        __syncthreads();

        #pragma unroll 1
        for (int t = 0; t < Tz; ++t) {
            {
                int b = tid & 63, k = tid >> 6;
                const float* src = dec_x + ((size_t)(b0 + b) * Tz + t) * Dz;
                xs[k * RS + b]       = src[k];
                xs[(k + 4) * RS + b] = src[k + 4];
            }
            __syncthreads();
            layer_gates<36>(tid, WI0, WH0, db0, xs, hs0, gs);
            __syncthreads();
            layer_epilogue(tid, gs, cs0, hs0, (float*)0);
            __syncthreads();
            layer_gates<32>(tid, WI1, WH1, db1, hs0, hs1, gs);
            __syncthreads();
            layer_epilogue(tid, gs, cs1, hs1, (float*)0);
            __syncthreads();
            layer_gates<32>(tid, WI2, WH2, db2, hs1, hs2, gs);
            __syncthreads();
            layer_epilogue(tid, gs, cs2, hs2, ybuf);
            __syncthreads();

            fc_store(tid, hs2, fw, fb, out, b0, t);
        }
    }
}

extern "C" void kernel_launch(void* const* d_in, const int* in_sizes, int n_in,
                              void* d_out, int out_size) {
    (void)in_sizes; (void)n_in; (void)out_size;
    const float* enc_x = (const float*)d_in[0];
    const float* dec_x = (const float*)d_in[1];
    const float* eWih0 = (const float*)d_in[2];
    const float* eWhh0 = (const float*)d_in[3];
    const float* eb0   = (const float*)d_in[4];
    const float* eWih1 = (const float*)d_in[5];
    const float* eWhh1 = (const float*)d_in[6];
    const float* eb1   = (const float*)d_in[7];
    const float* eWih2 = (const float*)d_in[8];
    const float* eWhh2 = (const float*)d_in[9];
    const float* eb2   = (const float*)d_in[10];
    const float* dWih0 = (const float*)d_in[11];
    const float* dWhh0 = (const float*)d_in[12];
    const float* db0   = (const float*)d_in[13];
    const float* dWih1 = (const float*)d_in[14];
    const float* dWhh1 = (const float*)d_in[15];
    const float* db1   = (const float*)d_in[16];
    const float* dWih2 = (const float*)d_in[17];
    const float* dWhh2 = (const float*)d_in[18];
    const float* db2   = (const float*)d_in[19];
    const float* fcW   = (const float*)d_in[20];
    const float* fcb   = (const float*)d_in[21];
    float* out = (float*)d_out;

    // weight transpose+duplicate prep (12 tiny launches, graph-capturable)
    prep_kernel<<< 4, 256>>>(eWih0,  8, O_EI0);
    prep_kernel<<<32, 256>>>(eWhh0, 64, O_EH0);
    prep_kernel<<<32, 256>>>(eWih1, 64, O_EI1);
    prep_kernel<<<32, 256>>>(eWhh1, 64, O_EH1);
    prep_kernel<<<32, 256>>>(eWih2, 64, O_EI2);
    prep_kernel<<<32, 256>>>(eWhh2, 64, O_EH2);
    prep_kernel<<<36, 256>>>(dWih0, 72, O_DI0);
    prep_kernel<<<32, 256>>>(dWhh0, 64, O_DH0);
    prep_kernel<<<32, 256>>>(dWih1, 64, O_DI1);
    prep_kernel<<<32, 256>>>(dWhh1, 64, O_DH1);
    prep_kernel<<<32, 256>>>(dWih2, 64, O_DI2);
    prep_kernel<<<32, 256>>>(dWhh2, 64, O_DH2);

    cudaFuncSetAttribute(seq2seq_kernel,
                         cudaFuncAttributeMaxDynamicSharedMemorySize, SMEM_BYTES);
    seq2seq_kernel<<<NCTA, NTHR, SMEM_BYTES>>>(
        enc_x, dec_x, eb0, eb1, eb2, db0, db1, db2, fcW, fcb, out);
}

// round 10
// speedup vs baseline: 1.0857x; 1.0846x over previous
#include <cuda_runtime.h>
#include <cstdint>

// Problem constants
#define Bz   8192
#define Tz   512
#define Dz   8
#define Hz   64
#define Gz   256      // 4*H
#define BT   64       // batch tile per CTA
#define NCTA 128      // Bz / BT
#define NTHR 512

// SMEM layout (floats)
#define XROWS   72            // dec layer0 input = cat(x[8], y_prev[64])
#define RS      68            // row stride for xs/hs (rows 16B aligned: 68*4=272)
#define GSTR    66            // gs row stride (8B aligned, 2-way conflicts only)
#define XS_F    (XROWS*RS)            // 4896
#define HS_F    (3*Hz*RS)             // 13056
#define CS_F    (3*Hz*BT)             // 12288
#define GS_F    (Gz*GSTR)             // 16896
#define FW_F    (Dz*Hz)               // 512
#define SMEM_FLOATS (XS_F + HS_F + CS_F + GS_F + FW_F + 16)
#define SMEM_BYTES  (SMEM_FLOATS * 4)

typedef unsigned long long u64;

// Pre-transposed weights, NOT duplicated: element (k2*256 + j) = {W[j][2k2], W[j][2k2+1]}
__device__ float2 g_wt[92160];   // 737 KB

// offsets (float2 units) per matrix, fan2*256 each
#define O_EI0 0        // fan2=4
#define O_EH0 1024     // 32
#define O_EI1 9216     // 32
#define O_EH1 17408    // 32
#define O_EI2 25600    // 32
#define O_EH2 33792    // 32
#define O_DI0 41984    // 36
#define O_DH0 51200    // 32
#define O_DI1 59392    // 32
#define O_DH1 67584    // 32
#define O_DI2 75776    // 32
#define O_DH2 83968    // 32

// ---------------- helpers ----------------
__device__ __forceinline__ u64 pack2(float x, float y) {
    u64 r;
    asm("mov.b64 %0, {%1, %2};" : "=l"(r) : "r"(__float_as_uint(x)), "r"(__float_as_uint(y)));
    return r;
}
__device__ __forceinline__ u64 dup2(float x) {
    u64 r;
    asm("mov.b64 %0, {%1, %1};" : "=l"(r) : "r"(__float_as_uint(x)));
    return r;
}
__device__ __forceinline__ void ffma2(u64& a, u64 w, u64 v) {
    asm("fma.rn.f32x2 %0, %1, %2, %0;" : "+l"(a) : "l"(w), "l"(v));
}
__device__ __forceinline__ float tanhx(float x) {
    float r;
    asm("tanh.approx.f32 %0, %1;" : "=f"(r) : "f"(x));
    return r;
}
__device__ __forceinline__ float sigx(float x) {
    return fmaf(tanhx(0.5f * x), 0.5f, 0.5f);
}

// ---------------- fused weight prep: ONE launch ----------------
// grid = 360 blocks x 256 threads covers all 92160 float2 slots.
__global__ void prep_all(const float* __restrict__ p0, const float* __restrict__ p1,
                         const float* __restrict__ p2, const float* __restrict__ p3,
                         const float* __restrict__ p4, const float* __restrict__ p5,
                         const float* __restrict__ p6, const float* __restrict__ p7,
                         const float* __restrict__ p8, const float* __restrict__ p9,
                         const float* __restrict__ p10, const float* __restrict__ p11) {
    const float* ptrs[12] = {p0,p1,p2,p3,p4,p5,p6,p7,p8,p9,p10,p11};
    const int fans[12] = {8,64,64,64,64,64, 72,64,64,64,64,64};
    const int offs[12] = {O_EI0,O_EH0,O_EI1,O_EH1,O_EI2,O_EH2,
                          O_DI0,O_DH0,O_DI1,O_DH1,O_DI2,O_DH2};
    int rem = blockIdx.x * 256 + threadIdx.x;
    #pragma unroll
    for (int i = 0; i < 12; ++i) {
        int sz = (fans[i] >> 1) * 256;
        if (rem < sz) {
            int j = rem & 255, k2 = rem >> 8;
            const float* W = ptrs[i];
            g_wt[offs[i] + rem] = make_float2(W[j * fans[i] + 2 * k2],
                                             W[j * fans[i] + 2 * k2 + 1]);
            return;
        }
        rem -= sz;
    }
}

// ---------------- gate accumulation ----------------
// Thread handles rows jj and jj+128, batches [ho, ho+16).
template<int FAN2>
__device__ __forceinline__ void accum_mat(const float2* __restrict__ Wt, int jj,
                                          const float* __restrict__ s, int ho,
                                          u64* __restrict__ accA, u64* __restrict__ accB) {
    const float2* pA = Wt + jj;
    const float2* pB = Wt + jj + 128;
    float2 bufA[2], bufB[2];
    bufA[0] = pA[0]; bufB[0] = pB[0];
    if (FAN2 > 1) { bufA[1] = pA[256]; bufB[1] = pB[256]; }
    #pragma unroll 2
    for (int k2 = 0; k2 < FAN2; ++k2) {
        float2 wA = bufA[k2 & 1], wB = bufB[k2 & 1];
        if (k2 + 2 < FAN2) {
            bufA[k2 & 1] = pA[(k2 + 2) * 256];
            bufB[k2 & 1] = pB[(k2 + 2) * 256];
        }
        u64 wAx = dup2(wA.x), wAy = dup2(wA.y);
        u64 wBx = dup2(wB.x), wBy = dup2(wB.y);
        const ulonglong2* s0 = (const ulonglong2*)(s + (2 * k2) * RS + ho);
        const ulonglong2* s1 = (const ulonglong2*)(s + (2 * k2 + 1) * RS + ho);
        #pragma unroll
        for (int q = 0; q < 4; ++q) {
            ulonglong2 v0 = s0[q];
            ffma2(accA[2 * q],     wAx, v0.x);
            ffma2(accA[2 * q + 1], wAx, v0.y);
            ffma2(accB[2 * q],     wBx, v0.x);
            ffma2(accB[2 * q + 1], wBx, v0.y);
            ulonglong2 v1 = s1[q];
            ffma2(accA[2 * q],     wAy, v1.x);
            ffma2(accA[2 * q + 1], wAy, v1.y);
            ffma2(accB[2 * q],     wBy, v1.x);
            ffma2(accB[2 * q + 1], wBy, v1.y);
        }
    }
}

template<int FANIH2>
__device__ __forceinline__ void layer_gates(int tid,
                                            const float2* __restrict__ WtIh,
                                            const float2* __restrict__ WtHh,
                                            const float* __restrict__ bias,
                                            const float* __restrict__ in_s,
                                            const float* __restrict__ h_s,
                                            float* __restrict__ gs) {
    int jj = tid & 127, qd = tid >> 7, ho = qd * 16;
    u64 accA[8], accB[8];
    float bA = bias[jj], bB = bias[jj + 128];
    u64 bpA = pack2(bA, bA), bpB = pack2(bB, bB);
    #pragma unroll
    for (int i = 0; i < 8; ++i) { accA[i] = bpA; accB[i] = bpB; }
    accum_mat<FANIH2>(WtIh, jj, in_s, ho, accA, accB);
    accum_mat<32>(WtHh, jj, h_s, ho, accA, accB);
    float* gA = gs + jj * GSTR + ho;
    float* gB = gs + (jj + 128) * GSTR + ho;
    #pragma unroll
    for (int q = 0; q < 8; ++q) {
        *(u64*)(gA + 2 * q) = accA[q];
        *(u64*)(gB + 2 * q) = accB[q];
    }
}

// LSTM pointwise epilogue: thread handles unit u = tid&63, batch group tid>>6 (8 b each)
__device__ __forceinline__ void layer_epilogue(int tid,
                                               const float* __restrict__ gs,
                                               float* __restrict__ c_s,   // [b*64+u]
                                               float* __restrict__ h_s,   // [u*RS+b]
                                               float* __restrict__ y_s) { // optional copy
    int u = tid & 63, grp = tid >> 6;
    #pragma unroll 4
    for (int bi = 0; bi < 8; ++bi) {
        int b = grp * 8 + bi;
        float gi = gs[u * GSTR + b];
        float gf = gs[(u + 64) * GSTR + b];
        float gg = gs[(u + 128) * GSTR + b];
        float go = gs[(u + 192) * GSTR + b];
        float c  = c_s[b * Hz + u];
        float cn = sigx(gf) * c + sigx(gi) * tanhx(gg);
        float hn = sigx(go) * tanhx(cn);
        c_s[b * Hz + u] = cn;
        h_s[u * RS + b] = hn;
        if (y_s) y_s[u * RS + b] = hn;
    }
}

// Final FC: thread handles (b = tid>>3, d = tid&7); warp store spans 4 lines only.
__device__ __forceinline__ void fc_store(int tid,
                                         const float* __restrict__ h_s,
                                         const float* __restrict__ fw,
                                         const float* __restrict__ fb,
                                         float* __restrict__ out,
                                         int b0, int t) {
    int d = tid & 7, b = tid >> 3;
    float a = fb[d];
    #pragma unroll
    for (int u = 0; u < Hz; ++u)
        a = fmaf(fw[d * Hz + u], h_s[u * RS + b], a);
    out[((size_t)(b0 + b) * Tz + t) * Dz + d] = a;
}

__global__ void __launch_bounds__(NTHR, 1)
seq2seq_kernel(const float* __restrict__ enc_x, const float* __restrict__ dec_x,
               const float* __restrict__ eb0, const float* __restrict__ eb1, const float* __restrict__ eb2,
               const float* __restrict__ db0, const float* __restrict__ db1, const float* __restrict__ db2,
               const float* __restrict__ fcW, const float* __restrict__ fcb,
               float* __restrict__ out) {
    extern __shared__ float sm[];
    float* xs = sm;                 // [XROWS][RS] layer-0 input, transposed
    float* hs = xs + XS_F;          // 3 x [64][RS] h state, transposed
    float* cs = hs + HS_F;          // 3 x [b*64+u]
    float* gs = cs + CS_F;          // [256][GSTR]
    float* fw = gs + GS_F;
    float* fb = fw + FW_F;

    const int tid = threadIdx.x;
    const int b0  = blockIdx.x * BT;

    for (int i = tid; i < HS_F; i += NTHR) hs[i] = 0.f;
    for (int i = tid; i < CS_F; i += NTHR) cs[i] = 0.f;
    for (int i = tid; i < FW_F; i += NTHR) fw[i] = fcW[i];
    if (tid < Dz) fb[tid] = fcb[tid];
    __syncthreads();

    float* hs0 = hs;          float* hs1 = hs + Hz * RS;  float* hs2 = hs + 2 * Hz * RS;
    float* cs0 = cs;          float* cs1 = cs + Hz * BT;  float* cs2 = cs + 2 * Hz * BT;

    // ---------------- encoder ----------------
    {
        const float2* WI0 = g_wt + O_EI0; const float2* WH0 = g_wt + O_EH0;
        const float2* WI1 = g_wt + O_EI1; const float2* WH1 = g_wt + O_EH1;
        const float2* WI2 = g_wt + O_EI2; const float2* WH2 = g_wt + O_EH2;

        #pragma unroll 1
        for (int t = 0; t < Tz; ++t) {
            {
                int b = tid & 63, k = tid >> 6;   // 64 b x 8 k = 512 threads
                xs[k * RS + b] = enc_x[((size_t)(b0 + b) * Tz + t) * Dz + k];
            }
            __syncthreads();
            layer_gates<4>(tid, WI0, WH0, eb0, xs, hs0, gs);
            __syncthreads();
            layer_epilogue(tid, gs, cs0, hs0, (float*)0);
            __syncthreads();
            layer_gates<32>(tid, WI1, WH1, eb1, hs0, hs1, gs);
            __syncthreads();
            layer_epilogue(tid, gs, cs1, hs1, (float*)0);
            __syncthreads();
            layer_gates<32>(tid, WI2, WH2, eb2, hs1, hs2, gs);
            __syncthreads();
            layer_epilogue(tid, gs, cs2, hs2, (float*)0);
            __syncthreads();
        }
    }

    // ---------------- decoder ----------------
    {
        const float2* WI0 = g_wt + O_DI0; const float2* WH0 = g_wt + O_DH0;
        const float2* WI1 = g_wt + O_DI1; const float2* WH1 = g_wt + O_DH1;
        const float2* WI2 = g_wt + O_DI2; const float2* WH2 = g_wt + O_DH2;
        float* ybuf = xs + Dz * RS;

        for (int i = tid; i < Hz * RS; i += NTHR) ybuf[i] = 0.f;  // y_prev = 0
        __syncthreads();

        #pragma unroll 1
        for (int t = 0; t < Tz; ++t) {
            {
                int b = tid & 63, k = tid >> 6;
                xs[k * RS + b] = dec_x[((size_t)(b0 + b) * Tz + t) * Dz + k];
            }
            __syncthreads();
            layer_gates<36>(tid, WI0, WH0, db0, xs, hs0, gs);
            __syncthreads();
            layer_epilogue(tid, gs, cs0, hs0, (float*)0);
            __syncthreads();
            layer_gates<32>(tid, WI1, WH1, db1, hs0, hs1, gs);
            __syncthreads();
            layer_epilogue(tid, gs, cs1, hs1, (float*)0);
            __syncthreads();
            layer_gates<32>(tid, WI2, WH2, db2, hs1, hs2, gs);
            __syncthreads();
            layer_epilogue(tid, gs, cs2, hs2, ybuf);
            __syncthreads();

            fc_store(tid, hs2, fw, fb, out, b0, t);
        }
    }
}

extern "C" void kernel_launch(void* const* d_in, const int* in_sizes, int n_in,
                              void* d_out, int out_size) {
    (void)in_sizes; (void)n_in; (void)out_size;
    const float* enc_x = (const float*)d_in[0];
    const float* dec_x = (const float*)d_in[1];
    const float* eWih0 = (const float*)d_in[2];
    const float* eWhh0 = (const float*)d_in[3];
    const float* eb0   = (const float*)d_in[4];
    const float* eWih1 = (const float*)d_in[5];
    const float* eWhh1 = (const float*)d_in[6];
    const float* eb1   = (const float*)d_in[7];
    const float* eWih2 = (const float*)d_in[8];
    const float* eWhh2 = (const float*)d_in[9];
    const float* eb2   = (const float*)d_in[10];
    const float* dWih0 = (const float*)d_in[11];
    const float* dWhh0 = (const float*)d_in[12];
    const float* db0   = (const float*)d_in[13];
    const float* dWih1 = (const float*)d_in[14];
    const float* dWhh1 = (const float*)d_in[15];
    const float* db1   = (const float*)d_in[16];
    const float* dWih2 = (const float*)d_in[17];
    const float* dWhh2 = (const float*)d_in[18];
    const float* db2   = (const float*)d_in[19];
    const float* fcW   = (const float*)d_in[20];
    const float* fcb   = (const float*)d_in[21];
    float* out = (float*)d_out;

    // single fused weight-prep launch (keeps ncu -s 5 on the main kernel)
    prep_all<<<360, 256>>>(eWih0, eWhh0, eWih1, eWhh1, eWih2, eWhh2,
                           dWih0, dWhh0, dWih1, dWhh1, dWih2, dWhh2);

    cudaFuncSetAttribute(seq2seq_kernel,
                         cudaFuncAttributeMaxDynamicSharedMemorySize, SMEM_BYTES);
    seq2seq_kernel<<<NCTA, NTHR, SMEM_BYTES>>>(
        enc_x, dec_x, eb0, eb1, eb2, db0, db1, db2, fcW, fcb, out);
}

// round 11
// speedup vs baseline: 1.7063x; 1.5717x over previous
#include <cuda_runtime.h>
#include <cuda_fp16.h>
#include <cstdint>

// Problem constants
#define Bz   8192
#define Tz   512
#define Dz   8
#define Hz   64
#define Gz   256      // 4*H
#define BT   64       // batch tile per CTA
#define NCTA 128      // Bz / BT
#define NTHR 512

#define GSTR 66       // gs row stride (floats)
#define KPX  88       // xin kpad (halves)  -> conflict-free B-frag LDS
#define KPH  72       // h   kpad (halves)  -> conflict-free B-frag LDS

// ---- SMEM byte offsets (all 16B aligned) ----
#define GS_OFF   0                        // fp32 gs[256][GSTR]           67584 B
#define CS_OFF   67584                    // fp32 c[3][64][64]            49152 B
#define XHI_OFF  116736                   // half xin_hi[64][KPX]         11264 B
#define XLO_OFF  128000                   // half xin_lo[64][KPX]         11264 B
#define H0HI_OFF 139264                   // half h0_hi[64][KPH]           9216 B
#define H0LO_OFF 148480
#define H1HI_OFF 157696
#define H1LO_OFF 166912
#define H2HI_OFF 176128
#define H2LO_OFF 185344
#define FW_OFF   194560                   // fp32 fcW[8][64]               2048 B
#define FB_OFF   196608                   // fp32 fcb[8] (pad 64)            64 B
#define SB_OFF   196672                   // fp32 bias[6][256]             6144 B
#define SMEM_BYTES 202816

// ---- weight fragment arenas (A-frag order), hi/lo split ----
// element index = base + kt*512 + mt*32 + lane ; each uint4 = 4 regs of an A frag
#define NW 23552
__device__ uint4 g_whi[NW];
__device__ uint4 g_wlo[NW];

// per-matrix bases (uint4 units): kts = {1,4,4,4,4,4, 5,4,4,4,4,4}
#define B_EI0 0
#define B_EH0 512
#define B_EI1 2560
#define B_EH1 4608
#define B_EI2 6656
#define B_EH2 8704
#define B_DI0 10752
#define B_DH0 13312
#define B_DI1 15360
#define B_DH1 17408
#define B_DI2 19456
#define B_DH2 21504

// ---------------- helpers ----------------
__device__ __forceinline__ float tanhx(float x) {
    float r;
    asm("tanh.approx.f32 %0, %1;" : "=f"(r) : "f"(x));
    return r;
}
__device__ __forceinline__ float sigx(float x) {
    return fmaf(tanhx(0.5f * x), 0.5f, 0.5f);
}
__device__ __forceinline__ void mma16816(float c[4], uint4 a, unsigned b0, unsigned b1) {
    asm volatile("mma.sync.aligned.m16n8k16.row.col.f32.f16.f16.f32 "
                 "{%0,%1,%2,%3}, {%4,%5,%6,%7}, {%8,%9}, {%0,%1,%2,%3};"
                 : "+f"(c[0]), "+f"(c[1]), "+f"(c[2]), "+f"(c[3])
                 : "r"(a.x), "r"(a.y), "r"(a.z), "r"(a.w), "r"(b0), "r"(b1));
}
__device__ __forceinline__ void split16(float v, __half& hi, __half& lo) {
    hi = __float2half_rn(v);
    lo = __float2half_rn(v - __half2float(hi));
}

// ---------------- weight prep (one launch) ----------------
__global__ void prep_all(const float* __restrict__ p0, const float* __restrict__ p1,
                         const float* __restrict__ p2, const float* __restrict__ p3,
                         const float* __restrict__ p4, const float* __restrict__ p5,
                         const float* __restrict__ p6, const float* __restrict__ p7,
                         const float* __restrict__ p8, const float* __restrict__ p9,
                         const float* __restrict__ p10, const float* __restrict__ p11) {
    int id = blockIdx.x * 256 + threadIdx.x;
    if (id >= NW) return;
    const int kts[12]  = {1,4,4,4,4,4, 5,4,4,4,4,4};
    const int fans[12] = {8,64,64,64,64,64, 72,64,64,64,64,64};
    const float* ptrs[12] = {p0,p1,p2,p3,p4,p5,p6,p7,p8,p9,p10,p11};
    int m = 0, rel = id;
    #pragma unroll
    for (int i = 0; i < 12; ++i) {
        int sz = kts[i] * 512;
        if (rel >= sz && m == i) { rel -= sz; m = i + 1; }
    }
    int kt = rel >> 9, slot = rel & 511, mt = slot >> 5, lane = slot & 31;
    int fan = fans[m];
    const float* W = ptrs[m];
    unsigned hi4[4], lo4[4];
    #pragma unroll
    for (int r = 0; r < 4; ++r) {
        int row = mt * 16 + (lane >> 2) + (r & 1) * 8;
        int c0  = kt * 16 + (lane & 3) * 2 + (r >> 1) * 8;
        float w0 = (c0 < fan)     ? W[row * fan + c0]     : 0.f;
        float w1 = (c0 + 1 < fan) ? W[row * fan + c0 + 1] : 0.f;
        __half h0, l0, h1, l1;
        split16(w0, h0, l0);
        split16(w1, h1, l1);
        hi4[r] = (unsigned)__half_as_ushort(h0) | ((unsigned)__half_as_ushort(h1) << 16);
        lo4[r] = (unsigned)__half_as_ushort(l0) | ((unsigned)__half_as_ushort(l1) << 16);
    }
    g_whi[id] = make_uint4(hi4[0], hi4[1], hi4[2], hi4[3]);
    g_wlo[id] = make_uint4(lo4[0], lo4[1], lo4[2], lo4[3]);
}

// ---------------- MMA pass over one operand matrix ----------------
template<int NKT>
__device__ __forceinline__ void mma_pass(float c[8][4],
                                         const uint4* __restrict__ Ahi,
                                         const uint4* __restrict__ Alo,
                                         const __half* __restrict__ Bhi,
                                         const __half* __restrict__ Blo,
                                         int kpad, int mt, int lane) {
    const int ln4 = lane >> 2, lk = (lane & 3) * 2;
    const uint4* pHi = Ahi + mt * 32 + lane;
    const uint4* pLo = Alo + mt * 32 + lane;
    uint4 ahi = pHi[0], alo = pLo[0];
    #pragma unroll
    for (int kt = 0; kt < NKT; ++kt) {
        uint4 aH = ahi, aL = alo;
        if (kt + 1 < NKT) { ahi = pHi[(kt + 1) * 512]; alo = pLo[(kt + 1) * 512]; }
        const __half* bh = Bhi + ln4 * kpad + kt * 16 + lk;
        const __half* bl = Blo + ln4 * kpad + kt * 16 + lk;
        #pragma unroll
        for (int nt = 0; nt < 8; ++nt) {
            unsigned bh0 = *(const unsigned*)(bh + nt * 8 * kpad);
            unsigned bh1 = *(const unsigned*)(bh + nt * 8 * kpad + 8);
            unsigned bl0 = *(const unsigned*)(bl + nt * 8 * kpad);
            unsigned bl1 = *(const unsigned*)(bl + nt * 8 * kpad + 8);
            mma16816(c[nt], aH, bh0, bh1);   // hi*hi
            mma16816(c[nt], aL, bh0, bh1);   // lo*hi
            mma16816(c[nt], aH, bl0, bl1);   // hi*lo
        }
    }
}

// One layer's gates: all 16 warps, warp = m-tile
template<int NKT_IN>
__device__ __forceinline__ void layer_mma(int tid,
                                          const uint4* AIhi, const uint4* AIlo,
                                          const __half* BIhi, const __half* BIlo, int kpadIn,
                                          const uint4* AHhi, const uint4* AHlo,
                                          const __half* BHhi, const __half* BHlo,
                                          const float* __restrict__ bias,
                                          float* __restrict__ gs) {
    int mt = tid >> 5, lane = tid & 31;
    int r = lane >> 2, col = (lane & 3) * 2;
    float c[8][4];
    float bA = bias[mt * 16 + r], bB = bias[mt * 16 + r + 8];
    #pragma unroll
    for (int nt = 0; nt < 8; ++nt) { c[nt][0] = bA; c[nt][1] = bA; c[nt][2] = bB; c[nt][3] = bB; }
    mma_pass<NKT_IN>(c, AIhi, AIlo, BIhi, BIlo, kpadIn, mt, lane);
    mma_pass<4>(c, AHhi, AHlo, BHhi, BHlo, KPH, mt, lane);
    #pragma unroll
    for (int nt = 0; nt < 8; ++nt) {
        float* g0 = gs + (mt * 16 + r) * GSTR + nt * 8 + col;
        float* g1 = gs + (mt * 16 + r + 8) * GSTR + nt * 8 + col;
        *(float2*)g0 = make_float2(c[nt][0], c[nt][1]);
        *(float2*)g1 = make_float2(c[nt][2], c[nt][3]);
    }
}

// LSTM pointwise epilogue; writes fp16 split of h (and optionally y-feedback + fp32 h)
__device__ __forceinline__ void epilogue(int tid, const float* __restrict__ gs,
                                         float* __restrict__ c_s,
                                         __half* __restrict__ Hhi, __half* __restrict__ Hlo,
                                         __half* Yhi, __half* Ylo,       // xin+8 or null
                                         float* hf) {                    // gs rows 0..63 or null
    int u = tid & 63, grp = tid >> 6;
    #pragma unroll 4
    for (int bi = 0; bi < 8; ++bi) {
        int b = grp * 8 + bi;
        float gi = gs[u * GSTR + b];
        float gf = gs[(u + 64) * GSTR + b];
        float gg = gs[(u + 128) * GSTR + b];
        float go = gs[(u + 192) * GSTR + b];
        float cc = c_s[b * Hz + u];
        float cn = sigx(gf) * cc + sigx(gi) * tanhx(gg);
        float hn = sigx(go) * tanhx(cn);
        c_s[b * Hz + u] = cn;
        __half hi, lo;
        split16(hn, hi, lo);
        Hhi[b * KPH + u] = hi;
        Hlo[b * KPH + u] = lo;
        if (Yhi) { Yhi[b * KPX + u] = hi; Ylo[b * KPX + u] = lo; }
        if (hf)  hf[u * GSTR + b] = hn;
    }
}

__device__ __forceinline__ void fc_store(int tid, const float* __restrict__ hf,
                                         const float* __restrict__ fw,
                                         const float* __restrict__ fb,
                                         float* __restrict__ out, int b0, int t) {
    int d = tid & 7, b = tid >> 3;
    float a = fb[d];
    #pragma unroll
    for (int u = 0; u < Hz; ++u)
        a = fmaf(fw[d * Hz + u], hf[u * GSTR + b], a);
    out[((size_t)(b0 + b) * Tz + t) * Dz + d] = a;
}

__global__ void __launch_bounds__(NTHR, 1)
seq2seq_kernel(const float* __restrict__ enc_x, const float* __restrict__ dec_x,
               const float* __restrict__ eb0, const float* __restrict__ eb1, const float* __restrict__ eb2,
               const float* __restrict__ db0, const float* __restrict__ db1, const float* __restrict__ db2,
               const float* __restrict__ fcW, const float* __restrict__ fcb,
               float* __restrict__ out) {
    extern __shared__ __align__(16) char sm[];
    float* gs  = (float*)(sm + GS_OFF);
    float* cs  = (float*)(sm + CS_OFF);
    __half* xhi = (__half*)(sm + XHI_OFF);
    __half* xlo = (__half*)(sm + XLO_OFF);
    __half* h0hi = (__half*)(sm + H0HI_OFF); __half* h0lo = (__half*)(sm + H0LO_OFF);
    __half* h1hi = (__half*)(sm + H1HI_OFF); __half* h1lo = (__half*)(sm + H1LO_OFF);
    __half* h2hi = (__half*)(sm + H2HI_OFF); __half* h2lo = (__half*)(sm + H2LO_OFF);
    float* fw = (float*)(sm + FW_OFF);
    float* fb = (float*)(sm + FB_OFF);
    float* sb = (float*)(sm + SB_OFF);

    const int tid = threadIdx.x;
    const int b0  = blockIdx.x * BT;

    // init: zero state/input buffers, cache fc + biases
    for (int i = tid; i < 3 * Hz * BT; i += NTHR) cs[i] = 0.f;
    for (int i = tid; i < BT * KPX; i += NTHR) { xhi[i] = __ushort_as_half(0); xlo[i] = __ushort_as_half(0); }
    for (int i = tid; i < BT * KPH; i += NTHR) {
        h0hi[i] = __ushort_as_half(0); h0lo[i] = __ushort_as_half(0);
        h1hi[i] = __ushort_as_half(0); h1lo[i] = __ushort_as_half(0);
        h2hi[i] = __ushort_as_half(0); h2lo[i] = __ushort_as_half(0);
    }
    for (int i = tid; i < Dz * Hz; i += NTHR) fw[i] = fcW[i];
    if (tid < Dz) fb[tid] = fcb[tid];
    for (int i = tid; i < Gz; i += NTHR) {
        sb[i]           = eb0[i]; sb[Gz + i]     = eb1[i]; sb[2 * Gz + i] = eb2[i];
        sb[3 * Gz + i]  = db0[i]; sb[4 * Gz + i] = db1[i]; sb[5 * Gz + i] = db2[i];
    }
    __syncthreads();

    float* cs0 = cs; float* cs1 = cs + Hz * BT; float* cs2 = cs + 2 * Hz * BT;

    // ---------------- encoder ----------------
    #pragma unroll 1
    for (int t = 0; t < Tz; ++t) {
        {
            int b = tid & 63, k = tid >> 6;
            float v = enc_x[((size_t)(b0 + b) * Tz + t) * Dz + k];
            __half hi, lo; split16(v, hi, lo);
            xhi[b * KPX + k] = hi; xlo[b * KPX + k] = lo;
        }
        __syncthreads();
        layer_mma<1>(tid, g_whi + B_EI0, g_wlo + B_EI0, xhi, xlo, KPX,
                     g_whi + B_EH0, g_wlo + B_EH0, h0hi, h0lo, sb, gs);
        __syncthreads();
        epilogue(tid, gs, cs0, h0hi, h0lo, (__half*)0, (__half*)0, (float*)0);
        __syncthreads();
        layer_mma<4>(tid, g_whi + B_EI1, g_wlo + B_EI1, h0hi, h0lo, KPH,
                     g_whi + B_EH1, g_wlo + B_EH1, h1hi, h1lo, sb + Gz, gs);
        __syncthreads();
        epilogue(tid, gs, cs1, h1hi, h1lo, (__half*)0, (__half*)0, (float*)0);
        __syncthreads();
        layer_mma<4>(tid, g_whi + B_EI2, g_wlo + B_EI2, h1hi, h1lo, KPH,
                     g_whi + B_EH2, g_wlo + B_EH2, h2hi, h2lo, sb + 2 * Gz, gs);
        __syncthreads();
        epilogue(tid, gs, cs2, h2hi, h2lo, (__half*)0, (__half*)0, (float*)0);
        __syncthreads();
    }

    // ---------------- decoder ----------------
    // y_prev (xin cols 8..71) is still zero from init (encoder never wrote it)
    #pragma unroll 1
    for (int t = 0; t < Tz; ++t) {
        {
            int b = tid & 63, k = tid >> 6;
            float v = dec_x[((size_t)(b0 + b) * Tz + t) * Dz + k];
            __half hi, lo; split16(v, hi, lo);
            xhi[b * KPX + k] = hi; xlo[b * KPX + k] = lo;
        }
        __syncthreads();
        layer_mma<5>(tid, g_whi + B_DI0, g_wlo + B_DI0, xhi, xlo, KPX,
                     g_whi + B_DH0, g_wlo + B_DH0, h0hi, h0lo, sb + 3 * Gz, gs);
        __syncthreads();
        epilogue(tid, gs, cs0, h0hi, h0lo, (__half*)0, (__half*)0, (float*)0);
        __syncthreads();
        layer_mma<4>(tid, g_whi + B_DI1, g_wlo + B_DI1, h0hi, h0lo, KPH,
                     g_whi + B_DH1, g_wlo + B_DH1, h1hi, h1lo, sb + 4 * Gz, gs);
        __syncthreads();
        epilogue(tid, gs, cs1, h1hi, h1lo, (__half*)0, (__half*)0, (float*)0);
        __syncthreads();
        layer_mma<4>(tid, g_whi + B_DI2, g_wlo + B_DI2, h1hi, h1lo, KPH,
                     g_whi + B_DH2, g_wlo + B_DH2, h2hi, h2lo, sb + 5 * Gz, gs);
        __syncthreads();
        epilogue(tid, gs, cs2, h2hi, h2lo, xhi + 8, xlo + 8, gs);  // y-feedback + fp32 h in gs rows 0..63
        __syncthreads();

        fc_store(tid, gs, fw, fb, out, b0, t);
    }
}

extern "C" void kernel_launch(void* const* d_in, const int* in_sizes, int n_in,
                              void* d_out, int out_size) {
    (void)in_sizes; (void)n_in; (void)out_size;
    const float* enc_x = (const float*)d_in[0];
    const float* dec_x = (const float*)d_in[1];
    const float* eWih0 = (const float*)d_in[2];
    const float* eWhh0 = (const float*)d_in[3];
    const float* eb0   = (const float*)d_in[4];
    const float* eWih1 = (const float*)d_in[5];
    const float* eWhh1 = (const float*)d_in[6];
    const float* eb1   = (const float*)d_in[7];
    const float* eWih2 = (const float*)d_in[8];
    const float* eWhh2 = (const float*)d_in[9];
    const float* eb2   = (const float*)d_in[10];
    const float* dWih0 = (const float*)d_in[11];
    const float* dWhh0 = (const float*)d_in[12];
    const float* db0   = (const float*)d_in[13];
    const float* dWih1 = (const float*)d_in[14];
    const float* dWhh1 = (const float*)d_in[15];
    const float* db1   = (const float*)d_in[16];
    const float* dWih2 = (const float*)d_in[17];
    const float* dWhh2 = (const float*)d_in[18];
    const float* db2   = (const float*)d_in[19];
    const float* fcW   = (const float*)d_in[20];
    const float* fcb   = (const float*)d_in[21];
    float* out = (float*)d_out;

    // fragment-order hi/lo weight prep (ONE launch; order matches B_* bases)
    prep_all<<<92, 256>>>(eWih0, eWhh0, eWih1, eWhh1, eWih2, eWhh2,
                          dWih0, dWhh0, dWih1, dWhh1, dWih2, dWhh2);

    cudaFuncSetAttribute(seq2seq_kernel,
                         cudaFuncAttributeMaxDynamicSharedMemorySize, SMEM_BYTES);
    seq2seq_kernel<<<NCTA, NTHR, SMEM_BYTES>>>(
        enc_x, dec_x, eb0, eb1, eb2, db0, db1, db2, fcW, fcb, out);
}

// round 13
// speedup vs baseline: 1.8292x; 1.0720x over previous
#include <cuda_runtime.h>
#include <cuda_fp16.h>
#include <cstdint>

// Problem constants
#define Bz   8192
#define Tz   512
#define Dz   8
#define Hz   64
#define Gz   256      // 4*H
#define BT   64       // batch tile per CTA
#define NCTA 128      // Bz / BT
#define NTHR 512

#define GSTR 66       // gs row stride (floats)
#define KPX  88       // xin kpad (halves)  -> conflict-free ldmatrix rows
#define KPH  72       // h   kpad (halves)  -> conflict-free ldmatrix rows

// ---- SMEM byte offsets (all 16B aligned) ----
#define GS_OFF   0                        // fp32 gs[256][GSTR]           67584 B
#define CS_OFF   67584                    // fp32 c[3][64][64]            49152 B
#define XHI_OFF  116736                   // half xin_hi[64][KPX]         11264 B
#define XLO_OFF  128000                   // half xin_lo[64][KPX]         11264 B
#define H0HI_OFF 139264                   // half h0_hi[64][KPH]           9216 B
#define H0LO_OFF 148480
#define H1HI_OFF 157696
#define H1LO_OFF 166912
#define H2HI_OFF 176128
#define H2LO_OFF 185344
#define FW_OFF   194560                   // fp32 fcW[8][64]               2048 B
#define FB_OFF   196608                   // fp32 fcb[8] (pad 64)            64 B
#define SB_OFF   196672                   // fp32 bias[6][256]             6144 B
#define SMEM_BYTES 202816

// ---- weight fragment arenas (A-frag order), hi/lo split ----
// element index = base + kt*512 + mt*32 + lane ; each uint4 = 4 regs of an A frag
#define NW 23552
__device__ uint4 g_whi[NW];
__device__ uint4 g_wlo[NW];

// per-matrix bases (uint4 units): kts = {1,4,4,4,4,4, 5,4,4,4,4,4}
#define B_EI0 0
#define B_EH0 512
#define B_EI1 2560
#define B_EH1 4608
#define B_EI2 6656
#define B_EH2 8704
#define B_DI0 10752
#define B_DH0 13312
#define B_DI1 15360
#define B_DH1 17408
#define B_DI2 19456
#define B_DH2 21504

// ---------------- helpers ----------------
__device__ __forceinline__ float tanhx(float x) {
    float r;
    asm("tanh.approx.f32 %0, %1;" : "=f"(r) : "f"(x));
    return r;
}
__device__ __forceinline__ float sigx(float x) {
    return fmaf(tanhx(0.5f * x), 0.5f, 0.5f);
}
__device__ __forceinline__ void mma16816(float c[4], uint4 a, unsigned b0, unsigned b1) {
    asm volatile("mma.sync.aligned.m16n8k16.row.col.f32.f16.f16.f32 "
                 "{%0,%1,%2,%3}, {%4,%5,%6,%7}, {%8,%9}, {%0,%1,%2,%3};"
                 : "+f"(c[0]), "+f"(c[1]), "+f"(c[2]), "+f"(c[3])
                 : "r"(a.x), "r"(a.y), "r"(a.z), "r"(a.w), "r"(b0), "r"(b1));
}
__device__ __forceinline__ void ldsm_x4(unsigned r[4], uint32_t addr) {
    asm volatile("ldmatrix.sync.aligned.m8n8.x4.shared.b16 {%0,%1,%2,%3}, [%4];"
                 : "=r"(r[0]), "=r"(r[1]), "=r"(r[2]), "=r"(r[3]) : "r"(addr));
}
__device__ __forceinline__ uint32_t smem_u32(const void* p) {
    return (uint32_t)__cvta_generic_to_shared(p);
}
__device__ __forceinline__ void split16(float v, __half& hi, __half& lo) {
    hi = __float2half_rn(v);
    lo = __float2half_rn(v - __half2float(hi));
}

// ---------------- weight prep (one launch) ----------------
__global__ void prep_all(const float* __restrict__ p0, const float* __restrict__ p1,
                         const float* __restrict__ p2, const float* __restrict__ p3,
                         const float* __restrict__ p4, const float* __restrict__ p5,
                         const float* __restrict__ p6, const float* __restrict__ p7,
                         const float* __restrict__ p8, const float* __restrict__ p9,
                         const float* __restrict__ p10, const float* __restrict__ p11) {
    int id = blockIdx.x * 256 + threadIdx.x;
    if (id >= NW) return;
    const int kts[12]  = {1,4,4,4,4,4, 5,4,4,4,4,4};
    const int fans[12] = {8,64,64,64,64,64, 72,64,64,64,64,64};
    const float* ptrs[12] = {p0,p1,p2,p3,p4,p5,p6,p7,p8,p9,p10,p11};
    int m = 0, rel = id;
    #pragma unroll
    for (int i = 0; i < 12; ++i) {
        int sz = kts[i] * 512;
        if (rel >= sz && m == i) { rel -= sz; m = i + 1; }
    }
    int kt = rel >> 9, slot = rel & 511, mt = slot >> 5, lane = slot & 31;
    int fan = fans[m];
    const float* W = ptrs[m];
    unsigned hi4[4], lo4[4];
    #pragma unroll
    for (int r = 0; r < 4; ++r) {
        int row = mt * 16 + (lane >> 2) + (r & 1) * 8;
        int c0  = kt * 16 + (lane & 3) * 2 + (r >> 1) * 8;
        float w0 = (c0 < fan)     ? W[row * fan + c0]     : 0.f;
        float w1 = (c0 + 1 < fan) ? W[row * fan + c0 + 1] : 0.f;
        __half h0, l0, h1, l1;
        split16(w0, h0, l0);
        split16(w1, h1, l1);
        hi4[r] = (unsigned)__half_as_ushort(h0) | ((unsigned)__half_as_ushort(h1) << 16);
        lo4[r] = (unsigned)__half_as_ushort(l0) | ((unsigned)__half_as_ushort(l1) << 16);
    }
    g_whi[id] = make_uint4(hi4[0], hi4[1], hi4[2], hi4[3]);
    g_wlo[id] = make_uint4(lo4[0], lo4[1], lo4[2], lo4[3]);
}

// ---------------- MMA pass over one operand matrix ----------------
// Warp tile: 2 m-tiles (mtg, mtg+1) x 4 n-tiles. B via ldmatrix.x4, A via LDG
// from fragment arenas with 1-deep double buffering.
template<int NKT>
__device__ __forceinline__ void mma_pass(float c[2][4][4],
                                         const uint4* __restrict__ Ahi,
                                         const uint4* __restrict__ Alo,
                                         int mtg, int lane,
                                         uint32_t bHi0, uint32_t bHi1,
                                         uint32_t bLo0, uint32_t bLo1) {
    const uint4* p0h = Ahi + mtg * 32 + lane;
    const uint4* p1h = p0h + 32;
    const uint4* p0l = Alo + mtg * 32 + lane;
    const uint4* p1l = p0l + 32;
    uint4 a0h = p0h[0], a1h = p1h[0], a0l = p0l[0], a1l = p1l[0];
    #pragma unroll
    for (int kt = 0; kt < NKT; ++kt) {
        uint4 A0h = a0h, A1h = a1h, A0l = a0l, A1l = a1l;
        if (kt + 1 < NKT) {
            a0h = p0h[(kt + 1) * 512]; a1h = p1h[(kt + 1) * 512];
            a0l = p0l[(kt + 1) * 512]; a1l = p1l[(kt + 1) * 512];
        }
        unsigned bh[8], bl[8];
        ldsm_x4(bh,     bHi0 + kt * 32);   // n-tiles 0,1 (b0,b1 each)
        ldsm_x4(bh + 4, bHi1 + kt * 32);   // n-tiles 2,3
        ldsm_x4(bl,     bLo0 + kt * 32);
        ldsm_x4(bl + 4, bLo1 + kt * 32);
        #pragma unroll
        for (int ntp = 0; ntp < 4; ++ntp) {
            unsigned h0 = bh[2 * ntp], h1 = bh[2 * ntp + 1];
            unsigned l0 = bl[2 * ntp], l1 = bl[2 * ntp + 1];
            mma16816(c[0][ntp], A0h, h0, h1);
            mma16816(c[0][ntp], A0l, h0, h1);
            mma16816(c[0][ntp], A0h, l0, l1);
            mma16816(c[1][ntp], A1h, h0, h1);
            mma16816(c[1][ntp], A1l, h0, h1);
            mma16816(c[1][ntp], A1h, l0, l1);
        }
    }
}

// lane-specific ldmatrix base address (bytes) for kt=0, n-rows [nb, nb+16)
__device__ __forceinline__ uint32_t ldsm_base(const __half* B, int kpad, int nb, int lane) {
    int r8 = lane & 7, kh = (lane >> 3) & 1, nh = (lane >> 4) & 1;
    int off = (nb + r8 + nh * 8) * kpad + kh * 8;   // halves
    return smem_u32(B) + (uint32_t)off * 2;
}

// One layer's gates: warp w -> m-tiles {2*(w>>1), 2*(w>>1)+1}, n-tiles (w&1)*4..+3
template<int NKT_IN>
__device__ __forceinline__ void layer_mma(int tid,
                                          const uint4* AIhi, const uint4* AIlo,
                                          const __half* BIhi, const __half* BIlo, int kpadIn,
                                          const uint4* AHhi, const uint4* AHlo,
                                          const __half* BHhi, const __half* BHlo,
                                          const float* __restrict__ bias,
                                          float* __restrict__ gs) {
    int w = tid >> 5, lane = tid & 31;
    int mtg = (w >> 1) * 2, nb = (w & 1) * 32;
    int r = lane >> 2, col = (lane & 3) * 2;

    float c[2][4][4];
    #pragma unroll
    for (int mt = 0; mt < 2; ++mt) {
        float bA = bias[(mtg + mt) * 16 + r], bB = bias[(mtg + mt) * 16 + r + 8];
        #pragma unroll
        for (int ntp = 0; ntp < 4; ++ntp) {
            c[mt][ntp][0] = bA; c[mt][ntp][1] = bA;
            c[mt][ntp][2] = bB; c[mt][ntp][3] = bB;
        }
    }
    {
        uint32_t hi0 = ldsm_base(BIhi, kpadIn, nb, lane);
        uint32_t lo0 = ldsm_base(BIlo, kpadIn, nb, lane);
        uint32_t step = (uint32_t)(16 * kpadIn * 2);
        mma_pass<NKT_IN>(c, AIhi, AIlo, mtg, lane, hi0, hi0 + step, lo0, lo0 + step);
    }
    {
        uint32_t hi0 = ldsm_base(BHhi, KPH, nb, lane);
        uint32_t lo0 = ldsm_base(BHlo, KPH, nb, lane);
        uint32_t step = (uint32_t)(16 * KPH * 2);
        mma_pass<4>(c, AHhi, AHlo, mtg, lane, hi0, hi0 + step, lo0, lo0 + step);
    }
    #pragma unroll
    for (int mt = 0; mt < 2; ++mt) {
        #pragma unroll
        for (int ntp = 0; ntp < 4; ++ntp) {
            float* g0 = gs + ((mtg + mt) * 16 + r) * GSTR + nb + ntp * 8 + col;
            float* g1 = g0 + 8 * GSTR;
            *(float2*)g0 = make_float2(c[mt][ntp][0], c[mt][ntp][1]);
            *(float2*)g1 = make_float2(c[mt][ntp][2], c[mt][ntp][3]);
        }
    }
}

// LSTM pointwise epilogue; writes fp16 split of h (and optionally y-feedback + fp32 h)
__device__ __forceinline__ void epilogue(int tid, const float* __restrict__ gs,
                                         float* __restrict__ c_s,
                                         __half* __restrict__ Hhi, __half* __restrict__ Hlo,
                                         __half* Yhi, __half* Ylo,       // xin+8 or null
                                         float* hf) {                    // gs rows 0..63 or null
    int u = tid & 63, grp = tid >> 6;
    #pragma unroll 4
    for (int bi = 0; bi < 8; ++bi) {
        int b = grp * 8 + bi;
        float gi = gs[u * GSTR + b];
        float gf = gs[(u + 64) * GSTR + b];
        float gg = gs[(u + 128) * GSTR + b];
        float go = gs[(u + 192) * GSTR + b];
        float cc = c_s[b * Hz + u];
        float cn = sigx(gf) * cc + sigx(gi) * tanhx(gg);
        float hn = sigx(go) * tanhx(cn);
        c_s[b * Hz + u] = cn;
        __half hi, lo;
        split16(hn, hi, lo);
        Hhi[b * KPH + u] = hi;
        Hlo[b * KPH + u] = lo;
        if (Yhi) { Yhi[b * KPX + u] = hi; Ylo[b * KPX + u] = lo; }
        if (hf)  hf[u * GSTR + b] = hn;
    }
}

__device__ __forceinline__ void fc_store(int tid, const float* __restrict__ hf,
                                         const float* __restrict__ fw,
                                         const float* __restrict__ fb,
                                         float* __restrict__ out, int b0, int t) {
    int d = tid & 7, b = tid >> 3;
    float a = fb[d];
    #pragma unroll
    for (int u = 0; u < Hz; ++u)
        a = fmaf(fw[d * Hz + u], hf[u * GSTR + b], a);
    out[((size_t)(b0 + b) * Tz + t) * Dz + d] = a;
}

__global__ void __launch_bounds__(NTHR, 1)
seq2seq_kernel(const float* __restrict__ enc_x, const float* __restrict__ dec_x,
               const float* __restrict__ eb0, const float* __restrict__ eb1, const float* __restrict__ eb2,
               const float* __restrict__ db0, const float* __restrict__ db1, const float* __restrict__ db2,
               const float* __restrict__ fcW, const float* __restrict__ fcb,
               float* __restrict__ out) {
    extern __shared__ __align__(16) char sm[];
    float* gs  = (float*)(sm + GS_OFF);
    float* cs  = (float*)(sm + CS_OFF);
    __half* xhi = (__half*)(sm + XHI_OFF);
    __half* xlo = (__half*)(sm + XLO_OFF);
    __half* h0hi = (__half*)(sm + H0HI_OFF); __half* h0lo = (__half*)(sm + H0LO_OFF);
    __half* h1hi = (__half*)(sm + H1HI_OFF); __half* h1lo = (__half*)(sm + H1LO_OFF);
    __half* h2hi = (__half*)(sm + H2HI_OFF); __half* h2lo = (__half*)(sm + H2LO_OFF);
    float* fw = (float*)(sm + FW_OFF);
    float* fb = (float*)(sm + FB_OFF);
    float* sb = (float*)(sm + SB_OFF);

    const int tid = threadIdx.x;
    const int b0  = blockIdx.x * BT;

    // init: zero state/input buffers, cache fc + biases
    for (int i = tid; i < 3 * Hz * BT; i += NTHR) cs[i] = 0.f;
    for (int i = tid; i < BT * KPX; i += NTHR) { xhi[i] = __ushort_as_half(0); xlo[i] = __ushort_as_half(0); }
    for (int i = tid; i < BT * KPH; i += NTHR) {
        h0hi[i] = __ushort_as_half(0); h0lo[i] = __ushort_as_half(0);
        h1hi[i] = __ushort_as_half(0); h1lo[i] = __ushort_as_half(0);
        h2hi[i] = __ushort_as_half(0); h2lo[i] = __ushort_as_half(0);
    }
    for (int i = tid; i < Dz * Hz; i += NTHR) fw[i] = fcW[i];
    if (tid < Dz) fb[tid] = fcb[tid];
    for (int i = tid; i < Gz; i += NTHR) {
        sb[i]           = eb0[i]; sb[Gz + i]     = eb1[i]; sb[2 * Gz + i] = eb2[i];
        sb[3 * Gz + i]  = db0[i]; sb[4 * Gz + i] = db1[i]; sb[5 * Gz + i] = db2[i];
    }
    __syncthreads();

    float* cs0 = cs; float* cs1 = cs + Hz * BT; float* cs2 = cs + 2 * Hz * BT;

    // ---------------- encoder ----------------
    #pragma unroll 1
    for (int t = 0; t < Tz; ++t) {
        {
            int b = tid & 63, k = tid >> 6;
            float v = enc_x[((size_t)(b0 + b) * Tz + t) * Dz + k];
            __half hi, lo; split16(v, hi, lo);
            xhi[b * KPX + k] = hi; xlo[b * KPX + k] = lo;
        }
        __syncthreads();
        layer_mma<1>(tid, g_whi + B_EI0, g_wlo + B_EI0, xhi, xlo, KPX,
                     g_whi + B_EH0, g_wlo + B_EH0, h0hi, h0lo, sb, gs);
        __syncthreads();
        epilogue(tid, gs, cs0, h0hi, h0lo, (__half*)0, (__half*)0, (float*)0);
        __syncthreads();
        layer_mma<4>(tid, g_whi + B_EI1, g_wlo + B_EI1, h0hi, h0lo, KPH,
                     g_whi + B_EH1, g_wlo + B_EH1, h1hi, h1lo, sb + Gz, gs);
        __syncthreads();
        epilogue(tid, gs, cs1, h1hi, h1lo, (__half*)0, (__half*)0, (float*)0);
        __syncthreads();
        layer_mma<4>(tid, g_whi + B_EI2, g_wlo + B_EI2, h1hi, h1lo, KPH,
                     g_whi + B_EH2, g_wlo + B_EH2, h2hi, h2lo, sb + 2 * Gz, gs);
        __syncthreads();
        epilogue(tid, gs, cs2, h2hi, h2lo, (__half*)0, (__half*)0, (float*)0);
        __syncthreads();
    }

    // ---------------- decoder ----------------
    // y_prev (xin cols 8..71) is still zero from init (encoder never wrote it)
    #pragma unroll 1
    for (int t = 0; t < Tz; ++t) {
        {
            int b = tid & 63, k = tid >> 6;
            float v = dec_x[((size_t)(b0 + b) * Tz + t) * Dz + k];
            __half hi, lo; split16(v, hi, lo);
            xhi[b * KPX + k] = hi; xlo[b * KPX + k] = lo;
        }
        __syncthreads();
        layer_mma<5>(tid, g_whi + B_DI0, g_wlo + B_DI0, xhi, xlo, KPX,
                     g_whi + B_DH0, g_wlo + B_DH0, h0hi, h0lo, sb + 3 * Gz, gs);
        __syncthreads();
        epilogue(tid, gs, cs0, h0hi, h0lo, (__half*)0, (__half*)0, (float*)0);
        __syncthreads();
        layer_mma<4>(tid, g_whi + B_DI1, g_wlo + B_DI1, h0hi, h0lo, KPH,
                     g_whi + B_DH1, g_wlo + B_DH1, h1hi, h1lo, sb + 4 * Gz, gs);
        __syncthreads();
        epilogue(tid, gs, cs1, h1hi, h1lo, (__half*)0, (__half*)0, (float*)0);
        __syncthreads();
        layer_mma<4>(tid, g_whi + B_DI2, g_wlo + B_DI2, h1hi, h1lo, KPH,
                     g_whi + B_DH2, g_wlo + B_DH2, h2hi, h2lo, sb + 5 * Gz, gs);
        __syncthreads();
        epilogue(tid, gs, cs2, h2hi, h2lo, xhi + 8, xlo + 8, gs);  // y-feedback + fp32 h in gs rows 0..63
        __syncthreads();

        fc_store(tid, gs, fw, fb, out, b0, t);
    }
}

extern "C" void kernel_launch(void* const* d_in, const int* in_sizes, int n_in,
                              void* d_out, int out_size) {
    (void)in_sizes; (void)n_in; (void)out_size;
    const float* enc_x = (const float*)d_in[0];
    const float* dec_x = (const float*)d_in[1];
    const float* eWih0 = (const float*)d_in[2];
    const float* eWhh0 = (const float*)d_in[3];
    const float* eb0   = (const float*)d_in[4];
    const float* eWih1 = (const float*)d_in[5];
    const float* eWhh1 = (const float*)d_in[6];
    const float* eb1   = (const float*)d_in[7];
    const float* eWih2 = (const float*)d_in[8];
    const float* eWhh2 = (const float*)d_in[9];
    const float* eb2   = (const float*)d_in[10];
    const float* dWih0 = (const float*)d_in[11];
    const float* dWhh0 = (const float*)d_in[12];
    const float* db0   = (const float*)d_in[13];
    const float* dWih1 = (const float*)d_in[14];
    const float* dWhh1 = (const float*)d_in[15];
    const float* db1   = (const float*)d_in[16];
    const float* dWih2 = (const float*)d_in[17];
    const float* dWhh2 = (const float*)d_in[18];
    const float* db2   = (const float*)d_in[19];
    const float* fcW   = (const float*)d_in[20];
    const float* fcb   = (const float*)d_in[21];
    float* out = (float*)d_out;

    // fragment-order hi/lo weight prep (ONE launch; order matches B_* bases)
    prep_all<<<92, 256>>>(eWih0, eWhh0, eWih1, eWhh1, eWih2, eWhh2,
                          dWih0, dWhh0, dWih1, dWhh1, dWih2, dWhh2);

    cudaFuncSetAttribute(seq2seq_kernel,
                         cudaFuncAttributeMaxDynamicSharedMemorySize, SMEM_BYTES);
    seq2seq_kernel<<<NCTA, NTHR, SMEM_BYTES>>>(
        enc_x, dec_x, eb0, eb1, eb2, db0, db1, db2, fcW, fcb, out);
}

// round 14
// speedup vs baseline: 2.7900x; 1.5253x over previous
#include <cuda_runtime.h>
#include <cuda_fp16.h>
#include <cstdint>

// Problem constants
#define Bz   8192
#define Tz   512
#define Dz   8
#define Hz   64
#define Gz   256      // 4*H
#define BT   64       // batch tile per CTA
#define NCTA 128      // Bz / BT
#define NTHR 512

#define KPX  88       // xin kpad (halves) -> conflict-free ldmatrix rows
#define KPH  72       // h   kpad (halves) -> conflict-free ldmatrix rows
#define GSW  36       // per-warp gate tile row stride (floats); 144B rows, 16B aligned

// ---- SMEM byte offsets ----
#define GS_OFF   0                    // per-warp gate tiles: 16 * 32*36*4 = 73728
#define XHI_OFF  73728                // half x[64][KPX]   11264
#define XLO_OFF  84992
#define H_OFF    96256                // 12 bufs (3 layer x 2 parity x hi/lo) of 64*KPH*2 = 9216
#define FW_OFF   206848               // fp32 fcW[8][64]   2048
#define FB_OFF   208896               // fp32 fcb          64
#define SB_OFF   208960               // fp32 permuted bias[6][256]  6144
#define SMEM_BYTES 215104

#define HBUF_B   9216

// ---- weight fragment arenas (A-frag order, PERMUTED rows), hi/lo split ----
// element index = base + kt*512 + mt*32 + lane
#define NW 23552
__device__ uint4 g_whi[NW];
__device__ uint4 g_wlo[NW];

// per-matrix bases (uint4 units): kts = {1,4,4,4,4,4, 5,4,4,4,4,4}
#define B_EI0 0
#define B_EH0 512
#define B_EI1 2560
#define B_EH1 4608
#define B_EI2 6656
#define B_EH2 8704
#define B_DI0 10752
#define B_DH0 13312
#define B_DI1 15360
#define B_DH1 17408
#define B_DI2 19456
#define B_DH2 21504

// per-CTA, per-layer fp32 c-state in global (L2-resident): [cta][layer][u*64+b]
__device__ float g_c[NCTA * 3 * 64 * 64];

// ---------------- helpers ----------------
__device__ __forceinline__ float tanhx(float x) {
    float r;
    asm("tanh.approx.f32 %0, %1;" : "=f"(r) : "f"(x));
    return r;
}
__device__ __forceinline__ float sigx(float x) {
    return fmaf(tanhx(0.5f * x), 0.5f, 0.5f);
}
__device__ __forceinline__ void mma16816(float c[4], uint4 a, unsigned b0, unsigned b1) {
    asm volatile("mma.sync.aligned.m16n8k16.row.col.f32.f16.f16.f32 "
                 "{%0,%1,%2,%3}, {%4,%5,%6,%7}, {%8,%9}, {%0,%1,%2,%3};"
                 : "+f"(c[0]), "+f"(c[1]), "+f"(c[2]), "+f"(c[3])
                 : "r"(a.x), "r"(a.y), "r"(a.z), "r"(a.w), "r"(b0), "r"(b1));
}
__device__ __forceinline__ void ldsm_x4(unsigned r[4], uint32_t addr) {
    asm volatile("ldmatrix.sync.aligned.m8n8.x4.shared.b16 {%0,%1,%2,%3}, [%4];"
                 : "=r"(r[0]), "=r"(r[1]), "=r"(r[2]), "=r"(r[3]) : "r"(addr));
}
__device__ __forceinline__ uint32_t smem_u32(const void* p) {
    return (uint32_t)__cvta_generic_to_shared(p);
}
__device__ __forceinline__ void split16(float v, __half& hi, __half& lo) {
    hi = __float2half_rn(v);
    lo = __float2half_rn(v - __half2float(hi));
}

// ---------------- weight prep (one launch), with gate-row permutation ----------------
// permuted row p: unit = p>>2, gate = p&3  =>  source row = 64*(p&3) + (p>>2)
__global__ void prep_all(const float* __restrict__ p0, const float* __restrict__ p1,
                         const float* __restrict__ p2, const float* __restrict__ p3,
                         const float* __restrict__ p4, const float* __restrict__ p5,
                         const float* __restrict__ p6, const float* __restrict__ p7,
                         const float* __restrict__ p8, const float* __restrict__ p9,
                         const float* __restrict__ p10, const float* __restrict__ p11) {
    int id = blockIdx.x * 256 + threadIdx.x;
    if (id >= NW) return;
    const int kts[12]  = {1,4,4,4,4,4, 5,4,4,4,4,4};
    const int fans[12] = {8,64,64,64,64,64, 72,64,64,64,64,64};
    const float* ptrs[12] = {p0,p1,p2,p3,p4,p5,p6,p7,p8,p9,p10,p11};
    int m = 0, rel = id;
    #pragma unroll
    for (int i = 0; i < 12; ++i) {
        int sz = kts[i] * 512;
        if (rel >= sz && m == i) { rel -= sz; m = i + 1; }
    }
    int kt = rel >> 9, slot = rel & 511, mt = slot >> 5, lane = slot & 31;
    int fan = fans[m];
    const float* W = ptrs[m];
    unsigned hi4[4], lo4[4];
    #pragma unroll
    for (int r = 0; r < 4; ++r) {
        int prow = mt * 16 + (lane >> 2) + (r & 1) * 8;
        int srow = 64 * (prow & 3) + (prow >> 2);      // gate-row permutation
        int c0   = kt * 16 + (lane & 3) * 2 + (r >> 1) * 8;
        float w0 = (c0 < fan)     ? W[srow * fan + c0]     : 0.f;
        float w1 = (c0 + 1 < fan) ? W[srow * fan + c0 + 1] : 0.f;
        __half h0, l0, h1, l1;
        split16(w0, h0, l0);
        split16(w1, h1, l1);
        hi4[r] = (unsigned)__half_as_ushort(h0) | ((unsigned)__half_as_ushort(h1) << 16);
        lo4[r] = (unsigned)__half_as_ushort(l0) | ((unsigned)__half_as_ushort(l1) << 16);
    }
    g_whi[id] = make_uint4(hi4[0], hi4[1], hi4[2], hi4[3]);
    g_wlo[id] = make_uint4(lo4[0], lo4[1], lo4[2], lo4[3]);
}

// ---------------- MMA pass over one operand matrix (unchanged core) ----------------
template<int NKT>
__device__ __forceinline__ void mma_pass(float c[2][4][4],
                                         const uint4* __restrict__ Ahi,
                                         const uint4* __restrict__ Alo,
                                         int mtg, int lane,
                                         uint32_t bHi0, uint32_t bHi1,
                                         uint32_t bLo0, uint32_t bLo1) {
    const uint4* p0h = Ahi + mtg * 32 + lane;
    const uint4* p1h = p0h + 32;
    const uint4* p0l = Alo + mtg * 32 + lane;
    const uint4* p1l = p0l + 32;
    uint4 a0h = p0h[0], a1h = p1h[0], a0l = p0l[0], a1l = p1l[0];
    #pragma unroll
    for (int kt = 0; kt < NKT; ++kt) {
        uint4 A0h = a0h, A1h = a1h, A0l = a0l, A1l = a1l;
        if (kt + 1 < NKT) {
            a0h = p0h[(kt + 1) * 512]; a1h = p1h[(kt + 1) * 512];
            a0l = p0l[(kt + 1) * 512]; a1l = p1l[(kt + 1) * 512];
        }
        unsigned bh[8], bl[8];
        ldsm_x4(bh,     bHi0 + kt * 32);
        ldsm_x4(bh + 4, bHi1 + kt * 32);
        ldsm_x4(bl,     bLo0 + kt * 32);
        ldsm_x4(bl + 4, bLo1 + kt * 32);
        #pragma unroll
        for (int ntp = 0; ntp < 4; ++ntp) {
            unsigned h0 = bh[2 * ntp], h1 = bh[2 * ntp + 1];
            unsigned l0 = bl[2 * ntp], l1 = bl[2 * ntp + 1];
            mma16816(c[0][ntp], A0h, h0, h1);
            mma16816(c[0][ntp], A0l, h0, h1);
            mma16816(c[0][ntp], A0h, l0, l1);
            mma16816(c[1][ntp], A1h, h0, h1);
            mma16816(c[1][ntp], A1l, h0, h1);
            mma16816(c[1][ntp], A1h, l0, l1);
        }
    }
}

// lane-specific ldmatrix base address (bytes) for kt=0, n-rows [nb, nb+16)
__device__ __forceinline__ uint32_t ldsm_base(const __half* B, int kpad, int nb, int lane) {
    int r8 = lane & 7, kh = (lane >> 3) & 1, nh = (lane >> 4) & 1;
    int off = (nb + r8 + nh * 8) * kpad + kh * 8;
    return smem_u32(B) + (uint32_t)off * 2;
}

// ---------------- fused layer: MMA + warp-local LSTM epilogue ----------------
// Warp w: m-tiles {2(w>>1), 2(w>>1)+1} (= units 8(w>>1)..+7, all 4 gates),
//         batches [32(w&1), +32). No __syncthreads inside; caller barriers after.
template<int NKT_IN, bool HAS_Y>
__device__ __forceinline__ void layer(int tid,
                                      const uint4* AIhi, const uint4* AIlo,
                                      const __half* BIhi, const __half* BIlo, int kpadIn,
                                      const uint4* AHhi, const uint4* AHlo,
                                      const __half* BHhi, const __half* BHlo,
                                      const float* __restrict__ sbP,
                                      float* __restrict__ cg, bool first,
                                      __half* __restrict__ Hhi, __half* __restrict__ Hlo,
                                      __half* Yhi, __half* Ylo,
                                      float* __restrict__ gsAll) {
    const int w = tid >> 5, lane = tid & 31;
    const int mtg = (w >> 1) * 2, nb = (w & 1) * 32;
    const int r = lane >> 2, q = lane & 3;
    float* gsw = gsAll + w * (32 * GSW);

    // c-state prefetch (global, L2-resident; latency hides under MMA)
    const int ub = 8 * (w >> 1) + r;      // global unit owned by this lane
    const int bb = nb + q * 8;            // base batch owned by this lane
    float4 cA, cB;
    if (first) { cA = make_float4(0.f, 0.f, 0.f, 0.f); cB = cA; }
    else { cA = *(const float4*)(cg + ub * 64 + bb);
           cB = *(const float4*)(cg + ub * 64 + bb + 4); }

    float c[2][4][4];
    #pragma unroll
    for (int mt = 0; mt < 2; ++mt) {
        float bA = sbP[(mtg + mt) * 16 + r], bB = sbP[(mtg + mt) * 16 + r + 8];
        #pragma unroll
        for (int ntp = 0; ntp < 4; ++ntp) {
            c[mt][ntp][0] = bA; c[mt][ntp][1] = bA;
            c[mt][ntp][2] = bB; c[mt][ntp][3] = bB;
        }
    }
    {
        uint32_t hi0 = ldsm_base(BIhi, kpadIn, nb, lane);
        uint32_t lo0 = ldsm_base(BIlo, kpadIn, nb, lane);
        uint32_t step = (uint32_t)(16 * kpadIn * 2);
        mma_pass<NKT_IN>(c, AIhi, AIlo, mtg, lane, hi0, hi0 + step, lo0, lo0 + step);
    }
    {
        uint32_t hi0 = ldsm_base(BHhi, KPH, nb, lane);
        uint32_t lo0 = ldsm_base(BHlo, KPH, nb, lane);
        uint32_t step = (uint32_t)(16 * KPH * 2);
        mma_pass<4>(c, AHhi, AHlo, mtg, lane, hi0, hi0 + step, lo0, lo0 + step);
    }

    // gates -> private warp tile (rows local 0..31 = 4*unitlocal + gate)
    #pragma unroll
    for (int mt = 0; mt < 2; ++mt)
        #pragma unroll
        for (int ntp = 0; ntp < 4; ++ntp) {
            *(float2*)(gsw + (mt * 16 + r) * GSW + ntp * 8 + 2 * q) =
                make_float2(c[mt][ntp][0], c[mt][ntp][1]);
            *(float2*)(gsw + (mt * 16 + r + 8) * GSW + ntp * 8 + 2 * q) =
                make_float2(c[mt][ntp][2], c[mt][ntp][3]);
        }
    __syncwarp();

    // transpose read-back: lane -> unit ub, batches bb..bb+7, 4 gates
    float ga[4][8];
    #pragma unroll
    for (int g = 0; g < 4; ++g) {
        float4 v0 = *(const float4*)(gsw + (4 * r + g) * GSW + 8 * q);
        float4 v1 = *(const float4*)(gsw + (4 * r + g) * GSW + 8 * q + 4);
        ga[g][0] = v0.x; ga[g][1] = v0.y; ga[g][2] = v0.z; ga[g][3] = v0.w;
        ga[g][4] = v1.x; ga[g][5] = v1.y; ga[g][6] = v1.z; ga[g][7] = v1.w;
    }
    float cc[8] = {cA.x, cA.y, cA.z, cA.w, cB.x, cB.y, cB.z, cB.w};
    #pragma unroll
    for (int bi = 0; bi < 8; ++bi) {
        float cn = sigx(ga[1][bi]) * cc[bi] + sigx(ga[0][bi]) * tanhx(ga[2][bi]);
        float hn = sigx(ga[3][bi]) * tanhx(cn);
        cc[bi] = cn;
        __half hi, lo; split16(hn, hi, lo);
        Hhi[(bb + bi) * KPH + ub] = hi;
        Hlo[(bb + bi) * KPH + ub] = lo;
        if (HAS_Y) { Yhi[(bb + bi) * KPX + ub] = hi; Ylo[(bb + bi) * KPX + ub] = lo; }
    }
    *(float4*)(cg + ub * 64 + bb)     = make_float4(cc[0], cc[1], cc[2], cc[3]);
    *(float4*)(cg + ub * 64 + bb + 4) = make_float4(cc[4], cc[5], cc[6], cc[7]);
}

// x staging: 512 threads = 64 batches x 8 cols
__device__ __forceinline__ void stage_x(int tid, const float* __restrict__ xp,
                                        int b0, int t, __half* xhi, __half* xlo) {
    int b = tid & 63, k = tid >> 6;
    float v = xp[((size_t)(b0 + b) * Tz + t) * Dz + k];
    __half hi, lo; split16(v, hi, lo);
    xhi[b * KPX + k] = hi; xlo[b * KPX + k] = lo;
}

// fc for step t: reads h2 (hi+lo) buffers of given parity
__device__ __forceinline__ void fc_do(int tid, const __half* __restrict__ h2hi,
                                      const __half* __restrict__ h2lo,
                                      const float* __restrict__ fw,
                                      const float* __restrict__ fb,
                                      float* __restrict__ out, int b0, int t) {
    int d = tid & 7, b = tid >> 3;
    float a = fb[d];
    #pragma unroll
    for (int u2 = 0; u2 < 32; ++u2) {
        __half2 hh = *(const __half2*)(h2hi + b * KPH + 2 * u2);
        __half2 hl = *(const __half2*)(h2lo + b * KPH + 2 * u2);
        float2 fh = __half22float2(hh), fl = __half22float2(hl);
        a = fmaf(fw[d * 64 + 2 * u2],     fh.x + fl.x, a);
        a = fmaf(fw[d * 64 + 2 * u2 + 1], fh.y + fl.y, a);
    }
    out[((size_t)(b0 + b) * Tz + t) * Dz + d] = a;
}

__global__ void __launch_bounds__(NTHR, 1)
seq2seq_kernel(const float* __restrict__ enc_x, const float* __restrict__ dec_x,
               const float* __restrict__ eb0, const float* __restrict__ eb1, const float* __restrict__ eb2,
               const float* __restrict__ db0, const float* __restrict__ db1, const float* __restrict__ db2,
               const float* __restrict__ fcW, const float* __restrict__ fcb,
               float* __restrict__ out) {
    extern __shared__ __align__(16) char sm[];
    float* gs   = (float*)(sm + GS_OFF);
    __half* xhi = (__half*)(sm + XHI_OFF);
    __half* xlo = (__half*)(sm + XLO_OFF);
    float* fw = (float*)(sm + FW_OFF);
    float* fb = (float*)(sm + FB_OFF);
    float* sb = (float*)(sm + SB_OFF);

    const int tid = threadIdx.x;
    const int b0  = blockIdx.x * BT;

    // h buffer accessor: layer l, parity par, hi/lo
    __half* hb[3][2][2];
    #pragma unroll
    for (int l = 0; l < 3; ++l)
        #pragma unroll
        for (int par = 0; par < 2; ++par)
            #pragma unroll
            for (int hl = 0; hl < 2; ++hl)
                hb[l][par][hl] = (__half*)(sm + H_OFF + (((l * 2 + par) * 2 + hl) * HBUF_B));

    float* cg0 = g_c + ((size_t)blockIdx.x * 3 + 0) * 4096;
    float* cg1 = g_c + ((size_t)blockIdx.x * 3 + 1) * 4096;
    float* cg2 = g_c + ((size_t)blockIdx.x * 3 + 2) * 4096;

    // init: zero x + all h buffers, cache fc + permuted biases
    {
        uint32_t* xz = (uint32_t*)(sm + XHI_OFF);
        for (int i = tid; i < (2 * BT * KPX) / 2; i += NTHR) xz[i] = 0u;
        uint32_t* hz = (uint32_t*)(sm + H_OFF);
        for (int i = tid; i < (12 * HBUF_B) / 4; i += NTHR) hz[i] = 0u;
        for (int i = tid; i < Dz * Hz; i += NTHR) fw[i] = fcW[i];
        if (tid < Dz) fb[tid] = fcb[tid];
        for (int i = tid; i < Gz; i += NTHR) {
            int srow = 64 * (i & 3) + (i >> 2);        // permuted bias
            sb[i]            = eb0[srow];
            sb[Gz + i]       = eb1[srow];
            sb[2 * Gz + i]   = eb2[srow];
            sb[3 * Gz + i]   = db0[srow];
            sb[4 * Gz + i]   = db1[srow];
            sb[5 * Gz + i]   = db2[srow];
        }
        stage_x(tid, enc_x, b0, 0, xhi, xlo);
    }
    __syncthreads();

    // ---------------- encoder ----------------
    #pragma unroll 1
    for (int t = 0; t < Tz; ++t) {
        const int p = t & 1;
        // P0: layer 0 (in: x, h0[p]) -> h0[1-p]
        layer<1, false>(tid, g_whi + B_EI0, g_wlo + B_EI0, xhi, xlo, KPX,
                        g_whi + B_EH0, g_wlo + B_EH0, hb[0][p][0], hb[0][p][1],
                        sb, cg0, t == 0,
                        hb[0][1 - p][0], hb[0][1 - p][1], (__half*)0, (__half*)0, gs);
        __syncthreads();
        // P1: layer 1 (in: h0[1-p], h1[p]) -> h1[1-p]
        layer<4, false>(tid, g_whi + B_EI1, g_wlo + B_EI1, hb[0][1 - p][0], hb[0][1 - p][1], KPH,
                        g_whi + B_EH1, g_wlo + B_EH1, hb[1][p][0], hb[1][p][1],
                        sb + Gz, cg1, false,
                        hb[1][1 - p][0], hb[1][1 - p][1], (__half*)0, (__half*)0, gs);
        __syncthreads();
        // P2: stage next x (enc t+1, or dec t=0) + layer 2 -> h2[1-p]
        if (t < Tz - 1) stage_x(tid, enc_x, b0, t + 1, xhi, xlo);
        else            stage_x(tid, dec_x, b0, 0, xhi, xlo);
        layer<4, false>(tid, g_whi + B_EI2, g_wlo + B_EI2, hb[1][1 - p][0], hb[1][1 - p][1], KPH,
                        g_whi + B_EH2, g_wlo + B_EH2, hb[2][p][0], hb[2][p][1],
                        sb + 2 * Gz, cg2, false,
                        hb[2][1 - p][0], hb[2][1 - p][1], (__half*)0, (__half*)0, gs);
        __syncthreads();
    }

    // ---------------- decoder ----------------
    // encoder last write parity = 1-(511&1) = 0; dec t=0 reads p=0. y_prev cols zeroed at init.
    #pragma unroll 1
    for (int t = 0; t < Tz; ++t) {
        const int p = t & 1;
        // P0: layer 0 (in: x[cat], h0[p]) -> h0[1-p]; fc for t-1 overlaps
        layer<5, false>(tid, g_whi + B_DI0, g_wlo + B_DI0, xhi, xlo, KPX,
                        g_whi + B_DH0, g_wlo + B_DH0, hb[0][p][0], hb[0][p][1],
                        sb + 3 * Gz, cg0, false,
                        hb[0][1 - p][0], hb[0][1 - p][1], (__half*)0, (__half*)0, gs);
        if (t > 0) fc_do(tid, hb[2][p][0], hb[2][p][1], fw, fb, out, b0, t - 1);
        __syncthreads();
        // P1
        layer<4, false>(tid, g_whi + B_DI1, g_wlo + B_DI1, hb[0][1 - p][0], hb[0][1 - p][1], KPH,
                        g_whi + B_DH1, g_wlo + B_DH1, hb[1][p][0], hb[1][p][1],
                        sb + 4 * Gz, cg1, false,
                        hb[1][1 - p][0], hb[1][1 - p][1], (__half*)0, (__half*)0, gs);
        __syncthreads();
        // P2: stage dec x(t+1) + layer 2 with y-feedback into x cols 8..71
        if (t < Tz - 1) stage_x(tid, dec_x, b0, t + 1, xhi, xlo);
        layer<4, true>(tid, g_whi + B_DI2, g_wlo + B_DI2, hb[1][1 - p][0], hb[1][1 - p][1], KPH,
                       g_whi + B_DH2, g_wlo + B_DH2, hb[2][p][0], hb[2][p][1],
                       sb + 5 * Gz, cg2, false,
                       hb[2][1 - p][0], hb[2][1 - p][1], xhi + 8, xlo + 8, gs);
        __syncthreads();
    }
    // final output: t = 511 written at parity 0
    fc_do(tid, hb[2][0][0], hb[2][0][1], fw, fb, out, b0, Tz - 1);
}

extern "C" void kernel_launch(void* const* d_in, const int* in_sizes, int n_in,
                              void* d_out, int out_size) {
    (void)in_sizes; (void)n_in; (void)out_size;
    const float* enc_x = (const float*)d_in[0];
    const float* dec_x = (const float*)d_in[1];
    const float* eWih0 = (const float*)d_in[2];
    const float* eWhh0 = (const float*)d_in[3];
    const float* eb0   = (const float*)d_in[4];
    const float* eWih1 = (const float*)d_in[5];
    const float* eWhh1 = (const float*)d_in[6];
    const float* eb1   = (const float*)d_in[7];
    const float* eWih2 = (const float*)d_in[8];
    const float* eWhh2 = (const float*)d_in[9];
    const float* eb2   = (const float*)d_in[10];
    const float* dWih0 = (const float*)d_in[11];
    const float* dWhh0 = (const float*)d_in[12];
    const float* db0   = (const float*)d_in[13];
    const float* dWih1 = (const float*)d_in[14];
    const float* dWhh1 = (const float*)d_in[15];
    const float* db1   = (const float*)d_in[16];
    const float* dWih2 = (const float*)d_in[17];
    const float* dWhh2 = (const float*)d_in[18];
    const float* db2   = (const float*)d_in[19];
    const float* fcW   = (const float*)d_in[20];
    const float* fcb   = (const float*)d_in[21];
    float* out = (float*)d_out;

    // fragment-order hi/lo weight prep with gate-row permutation (ONE launch)
    prep_all<<<92, 256>>>(eWih0, eWhh0, eWih1, eWhh1, eWih2, eWhh2,
                          dWih0, dWhh0, dWih1, dWhh1, dWih2, dWhh2);

    cudaFuncSetAttribute(seq2seq_kernel,
                         cudaFuncAttributeMaxDynamicSharedMemorySize, SMEM_BYTES);
    seq2seq_kernel<<<NCTA, NTHR, SMEM_BYTES>>>(
        enc_x, dec_x, eb0, eb1, eb2, db0, db1, db2, fcW, fcb, out);
}